// round 9
// baseline (speedup 1.0000x reference)
#include <cuda_runtime.h>
#include <cstdint>
#include <math.h>

// Problem constants
#define BB    32
#define NQ    197
#define NV    1568
#define DIMD  768
#define HH    12
#define FF    8
#define NKC   196
#define NOUT  1569
#define BHN   384
#define KDIM  768

// ---------------- scratch (device globals) ----------------
__device__ float g_q[(size_t)BHN * NQ * 64];                 // scaled q heads layout (natural d)
__device__ float g_k[(size_t)BHN * NV * 64];
__device__ float g_v[(size_t)BHN * NV * 64];
__device__ float g_att[(size_t)BHN * NOUT * 64];             // natural layout
__device__ float g_qI[(size_t)BB * NQ * KDIM];               // question, permuted+rounded+0.125
__device__ float g_xI[(size_t)BB * NV * KDIM];               // x, permuted+rounded
__device__ float g_wqT[768 * 768];                           // W^T [N][K] permuted+rounded
__device__ float g_wkvT[1536 * 768];
__device__ float g_wpT[768 * 768];

// ======================= helpers =======================
__device__ __forceinline__ uint32_t smem_to_u32(const void* p) {
    uint32_t a;
    asm("{ .reg .u64 t; cvta.to.shared.u64 t, %1; cvt.u32.u64 %0, t; }" : "=r"(a) : "l"(p));
    return a;
}
__device__ __forceinline__ uint32_t to_tf32_rn(float x) {
    uint32_t r;
    asm("cvt.rn.tf32.f32 %0, %1;" : "=r"(r) : "f"(x));
    return r;
}
__device__ __forceinline__ float rnd_tf32(float x) { return __uint_as_float(to_tf32_rn(x)); }
__device__ __forceinline__ float4 f4_rnd(float4 v) {
    v.x = rnd_tf32(v.x); v.y = rnd_tf32(v.y); v.z = rnd_tf32(v.z); v.w = rnd_tf32(v.w);
    return v;
}
// pair-interleave position within 8-k groups: [k0,k4,k1,k5,k2,k6,k3,k7]
__device__ __forceinline__ int p8(int k) { return (k & ~7) | ((k & 3) << 1) | ((k >> 2) & 1); }
__device__ __forceinline__ void sts_pair8(float* dst, float4 v0, float4 v1) {
    *(float4*)dst       = make_float4(v0.x, v1.x, v0.y, v1.y);
    *(float4*)(dst + 4) = make_float4(v0.z, v1.z, v0.w, v1.w);
}
__device__ __forceinline__ void cp_async16(uint32_t smem_addr, const void* gptr) {
    asm volatile("cp.async.cg.shared.global [%0], [%1], 16;"
                 :: "r"(smem_addr), "l"(gptr));
}
__device__ __forceinline__ void cp_async16p(uint32_t smem_addr, const void* gptr, bool pred) {
    int sz = pred ? 16 : 0;
    asm volatile("cp.async.cg.shared.global [%0], [%1], 16, %2;"
                 :: "r"(smem_addr), "l"(gptr), "r"(sz));
}
#define CP_COMMIT() asm volatile("cp.async.commit_group;" ::: "memory")
#define CP_WAIT(n)  asm volatile("cp.async.wait_group %0;" :: "n"(n) : "memory")

__device__ __forceinline__ void mma_tf32(float* c, const uint32_t* a, const uint32_t* b) {
    asm volatile(
        "mma.sync.aligned.m16n8k8.row.col.f32.tf32.tf32.f32 "
        "{%0,%1,%2,%3}, {%4,%5,%6,%7}, {%8,%9}, {%0,%1,%2,%3};"
        : "+f"(c[0]), "+f"(c[1]), "+f"(c[2]), "+f"(c[3])
        : "r"(a[0]), "r"(a[1]), "r"(a[2]), "r"(a[3]), "r"(b[0]), "r"(b[1]));
}

// FMA-pipe exp
__device__ __forceinline__ float fast_exp(float x) {
    x = fmaxf(x, -87.0f);
    float y = x * 1.4426950408889634f;
    float r = y + 12582912.0f;
    int   n = __float_as_int(r) - 0x4B400000;
    float f = y - (r - 12582912.0f);
    float p = 1.3333558146e-3f;
    p = fmaf(p, f, 9.6181291076e-3f);
    p = fmaf(p, f, 5.5504108664e-2f);
    p = fmaf(p, f, 2.4022650696e-1f);
    p = fmaf(p, f, 6.9314718056e-1f);
    p = fmaf(p, f, 1.0f);
    return __int_as_float(__float_as_int(p) + (n << 23));
}

// ======================= A permute: round + pair-interleave (+scale) =======================
__global__ __launch_bounds__(256)
void permuteA(const float* __restrict__ src, float* __restrict__ dst,
              int nGroups, float scale)
{
    int g = blockIdx.x * 256 + threadIdx.x;
    if (g >= nGroups) return;
    const float4* s = (const float4*)src + (size_t)g * 2;
    float4 v0 = s[0], v1 = s[1];
    v0.x = rnd_tf32(v0.x * scale); v0.y = rnd_tf32(v0.y * scale);
    v0.z = rnd_tf32(v0.z * scale); v0.w = rnd_tf32(v0.w * scale);
    v1.x = rnd_tf32(v1.x * scale); v1.y = rnd_tf32(v1.y * scale);
    v1.z = rnd_tf32(v1.z * scale); v1.w = rnd_tf32(v1.w * scale);
    float4* d = (float4*)dst + (size_t)g * 2;
    d[0] = make_float4(v0.x, v1.x, v0.y, v1.y);
    d[1] = make_float4(v0.z, v1.z, v0.w, v1.w);
}

// ======================= weight transpose + tf32 round + pair-interleave =======================
__global__ __launch_bounds__(256)
void transposeW(const float* __restrict__ src, int which, int K, int N)
{
    float* dst = (which == 0) ? g_wqT : (which == 1) ? g_wkvT : g_wpT;
    __shared__ float t[32][33];
    int bx = blockIdx.x * 32;   // N block
    int by = blockIdx.y * 32;   // K block
    int txl = threadIdx.x & 31;
    int tyl = threadIdx.x >> 5;
#pragma unroll
    for (int j = 0; j < 32; j += 8)
        t[tyl + j][txl] = src[(size_t)(by + tyl + j) * N + bx + txl];
    __syncthreads();
#pragma unroll
    for (int j = 0; j < 32; j += 8)
        dst[(size_t)(bx + tyl + j) * K + by + p8(txl)] = rnd_tf32(t[txl][tyl + j]);
}

// ======================= mma.sync tf32 GEMM: 4-stage cp.async pipeline, BK=16 =======================
// MODE 0/1: A pre-permuted (g_qI/g_xI), stride 24, LDS.64 fragments, no CVT.
// MODE 2:   A natural (g_att gather), stride 20, LDS.32 + CVT.
// B: pre-interleaved weights, stride 24, LDS.64.
constexpr int BM = 128, BN = 128, BK = 16;
constexpr int SKB = 24;                          // (12g+t) mod 16 bijective per half-warp
constexpr int KT = KDIM / BK;                    // 48
constexpr int STAGES = 4;

template<int MODE>
__global__ __launch_bounds__(256, 2)
void gemm_tc(const float* __restrict__ A, const float* __restrict__ bias,
             float* __restrict__ Cout, int M)
{
    constexpr int SKA = (MODE == 2) ? 20 : 24;
    constexpr int A_WORDS = BM * SKA;
    constexpr int B_WORDS = BN * SKB;
    constexpr int STAGE_WORDS = A_WORDS + B_WORDS;

    extern __shared__ float sm[];
    const uint32_t sb32 = smem_to_u32(sm);
    const int tid   = threadIdx.x;
    const int warp  = tid >> 5;
    const int lane  = tid & 31;
    const int group = lane >> 2;
    const int tig   = lane & 3;
    const int wm    = warp & 3;
    const int wn    = warp >> 2;
    const int row0  = blockIdx.y * BM;
    const int col0  = blockIdx.x * BN;

    const float* BT = (MODE == 0) ? g_wqT : (MODE == 1) ? g_wkvT : g_wpT;

    float acc[2][8][4];
#pragma unroll
    for (int mt = 0; mt < 2; mt++)
#pragma unroll
        for (int nt = 0; nt < 8; nt++)
#pragma unroll
            for (int c = 0; c < 4; c++) acc[mt][nt][c] = 0.f;

    // per-thread cp.async coords: 4 float4 per 16-k row; 512 float4 per operand
    const int lr  = tid >> 2;          // 0..63 (two rows: lr, lr+64)
    const int lc4 = (tid & 3) << 2;    // word offset 0,4,8,12

    auto load_stage = [&](int kt, int s) {
        const uint32_t aoff = sb32 + (uint32_t)(s * STAGE_WORDS) * 4;
        const uint32_t boff = sb32 + (uint32_t)(s * STAGE_WORDS + A_WORDS) * 4;
        const int k0 = kt * BK;
#pragma unroll
        for (int it = 0; it < 2; it++) {
            int r = lr + it * 64;
            int grow = row0 + r;
            bool ok = grow < M;
            int gr = ok ? grow : 0;
            const float* src;
            if (MODE == 2) {
                int b_ = gr / NOUT;
                int n_ = gr - b_ * NOUT;
                int kk = k0 + lc4;
                int h = kk >> 6, dd = kk & 63;
                src = &g_att[(((size_t)(b_ * HH + h) * NOUT + n_) << 6) + dd];
            } else {
                src = &A[(size_t)gr * KDIM + k0 + lc4];
            }
            cp_async16p(aoff + (uint32_t)(r * SKA + lc4) * 4, src, ok);
        }
#pragma unroll
        for (int it = 0; it < 2; it++) {
            int r = lr + it * 64;
            cp_async16(boff + (uint32_t)(r * SKB + lc4) * 4,
                       &BT[(size_t)(col0 + r) * KDIM + k0 + lc4]);
        }
        CP_COMMIT();
    };

    // prologue: 3 stages in flight
    load_stage(0, 0);
    load_stage(1, 1);
    load_stage(2, 2);

    for (int kt = 0; kt < KT; kt++) {
        if (kt < KT - 2)      { CP_WAIT(2); }
        else if (kt == KT - 2){ CP_WAIT(1); }
        else                  { CP_WAIT(0); }
        __syncthreads();

        const float* As = sm + (kt & 3) * STAGE_WORDS;
        const float* Bs = As + A_WORDS;

#pragma unroll
        for (int ks = 0; ks < 2; ks++) {
            const int kc = ks * 8 + tig;        // natural (MODE 2 A)
            const int ko = ks * 8 + 2 * tig;    // interleaved
            uint32_t af[2][4];
#pragma unroll
            for (int mt = 0; mt < 2; mt++) {
                int r = wm * 32 + mt * 16 + group;
                if (MODE == 2) {
                    af[mt][0] = to_tf32_rn(As[r * SKA + kc]);
                    af[mt][1] = to_tf32_rn(As[(r + 8) * SKA + kc]);
                    af[mt][2] = to_tf32_rn(As[r * SKA + kc + 4]);
                    af[mt][3] = to_tf32_rn(As[(r + 8) * SKA + kc + 4]);
                } else {
                    float2 lo = *(const float2*)&As[r * SKA + ko];
                    float2 hi = *(const float2*)&As[(r + 8) * SKA + ko];
                    af[mt][0] = __float_as_uint(lo.x);
                    af[mt][1] = __float_as_uint(hi.x);
                    af[mt][2] = __float_as_uint(lo.y);
                    af[mt][3] = __float_as_uint(hi.y);
                }
            }
#pragma unroll
            for (int nt = 0; nt < 8; nt++) {
                int n = wn * 64 + nt * 8 + group;
                float2 b = *(const float2*)&Bs[n * SKB + ko];
                uint32_t bf[2] = { __float_as_uint(b.x), __float_as_uint(b.y) };
                mma_tf32(acc[0][nt], af[0], bf);
                mma_tf32(acc[1][nt], af[1], bf);
            }
        }

        if (kt + 3 < KT) load_stage(kt + 3, (kt + 3) & 3);
    }

    // ---- epilogue
#pragma unroll
    for (int mt = 0; mt < 2; mt++) {
#pragma unroll
        for (int half = 0; half < 2; half++) {
            int row = row0 + wm * 32 + mt * 16 + group + half * 8;
            if (row >= M) continue;
            int b_, n_;
            if (MODE == 0) { b_ = row / NQ;   n_ = row - b_ * NQ; }
            else if (MODE == 1) { b_ = row / NV; n_ = row - b_ * NV; }
            else { b_ = 0; n_ = 0; }
#pragma unroll
            for (int nt = 0; nt < 8; nt++) {
                int col = col0 + wn * 64 + nt * 8 + tig * 2;
                float v0 = acc[mt][nt][half * 2 + 0];
                float v1 = acc[mt][nt][half * 2 + 1];
                if (MODE == 0) {
                    int h = col >> 6, dd = col & 63;
                    *(float2*)&g_q[(((size_t)(b_ * HH + h) * NQ + n_) << 6) + dd] =
                        make_float2(v0, v1);   // 0.125 folded into g_qI
                } else if (MODE == 1) {
                    float2 w = make_float2(v0, v1);
                    if (col < DIMD) {
                        int h = col >> 6, dd = col & 63;
                        *(float2*)&g_k[(((size_t)(b_ * HH + h) * NV + n_) << 6) + dd] = w;
                    } else {
                        int c2 = col - DIMD;
                        int h = c2 >> 6, dd = c2 & 63;
                        *(float2*)&g_v[(((size_t)(b_ * HH + h) * NV + n_) << 6) + dd] = w;
                    }
                } else {
                    float2 w = make_float2(v0 + bias[col], v1 + bias[col + 1]);
                    *(float2*)&Cout[(size_t)row * DIMD + col] = w;
                }
            }
        }
    }
}

// ======================= cls-token attention =======================
__global__ __launch_bounds__(256)
void cls_attn()
{
    __shared__ float qsh[64];
    __shared__ float ssh[NV];
    __shared__ float red[40];
    __shared__ float osh[4][64];

    const int bh   = blockIdx.x;
    const int tid  = threadIdx.x;
    const int lane = tid & 31;
    const int warp = tid >> 5;

    if (tid < 64) qsh[tid] = g_q[((size_t)bh * NQ) * 64 + tid];
    __syncthreads();

    for (int j = warp; j < NV; j += 8) {
        const float* kr = &g_k[((size_t)bh * NV + j) * 64];
        float p = qsh[lane] * kr[lane] + qsh[lane + 32] * kr[lane + 32];
#pragma unroll
        for (int o = 16; o > 0; o >>= 1) p += __shfl_xor_sync(0xffffffffu, p, o);
        if (lane == 0) ssh[j] = p;
    }
    __syncthreads();

    float m = -1e30f;
    for (int j = tid; j < NV; j += 256) m = fmaxf(m, ssh[j]);
#pragma unroll
    for (int o = 16; o > 0; o >>= 1) m = fmaxf(m, __shfl_xor_sync(0xffffffffu, m, o));
    if (lane == 0) red[warp] = m;
    __syncthreads();
    if (tid == 0) {
        float mm = red[0];
        for (int w = 1; w < 8; w++) mm = fmaxf(mm, red[w]);
        red[32] = mm;
    }
    __syncthreads();
    m = red[32];

    float s = 0.f;
    for (int j = tid; j < NV; j += 256) {
        float e = fast_exp(ssh[j] - m);
        ssh[j] = e;
        s += e;
    }
#pragma unroll
    for (int o = 16; o > 0; o >>= 1) s += __shfl_xor_sync(0xffffffffu, s, o);
    if (lane == 0) red[8 + warp] = s;
    __syncthreads();
    if (tid == 0) {
        float ss = 0.f;
        for (int w = 0; w < 8; w++) ss += red[8 + w];
        red[33] = 1.f / ss;
    }
    __syncthreads();
    const float inv = red[33];

    const int g = tid >> 6, dd = tid & 63;
    float o = 0.f;
    for (int j = g; j < NV; j += 4)
        o = fmaf(ssh[j], g_v[((size_t)bh * NV + j) * 64 + dd], o);
    osh[g][dd] = o;
    __syncthreads();
    if (tid < 64) {
        float r = (osh[0][tid] + osh[1][tid] + osh[2][tid] + osh[3][tid]) * inv;
        g_att[((size_t)bh * NOUT) * 64 + tid] = r;
    }
}

// ======================= fine attention (R6 version) =======================
constexpr int QW = 72;    // Qs [64][72]  pair-interleaved d
constexpr int KW = 72;    // Ks [224][72] pair-interleaved d
constexpr int VW = 200;   // Vt [64][200] pair-interleaved keys
constexpr int SW = 228;   // Ss [64][228] natural
constexpr int Q_OFF = 0;
constexpr int K_OFF = Q_OFF + 64 * QW;
constexpr int V_OFF = K_OFF + 224 * KW;
constexpr int S_OFF = V_OFF + 64 * VW;
constexpr int I_OFF = S_OFF + 64 * SW;
constexpr int FINE_SMEM = (I_OFF + 64) * 4;

__global__ __launch_bounds__(256, 1)
void fine_attn()
{
    extern __shared__ float smf[];
    float* Qs = smf + Q_OFF;
    float* Ks = smf + K_OFF;
    float* Vt = smf + V_OFF;
    float* Ss = smf + S_OFF;
    float* Iv = smf + I_OFF;

    const int bh    = blockIdx.x >> 3;
    const int f     = blockIdx.x & 7;
    const int tid   = threadIdx.x;
    const int warp  = tid >> 5;
    const int lane  = tid & 31;
    const int group = lane >> 2;
    const int tig   = lane & 3;

    const float* kg = &g_k[((size_t)bh * NV + (size_t)f * NKC) * 64];
    const float* vg = &g_v[((size_t)bh * NV + (size_t)f * NKC) * 64];

    for (int u = tid; u < 224 * 8; u += 256) {
        int r = u >> 3, g = u & 7;
        float4 v0 = make_float4(0.f, 0.f, 0.f, 0.f), v1 = v0;
        if (r < NKC) {
            v0 = f4_rnd(*(const float4*)&kg[r * 64 + g * 8]);
            v1 = f4_rnd(*(const float4*)&kg[r * 64 + g * 8 + 4]);
        }
        sts_pair8(&Ks[r * KW + g * 8], v0, v1);
    }
    for (int idx = tid; idx < NKC * 16; idx += 256) {
        int j = idx >> 4, d4 = (idx & 15) << 2;
        *(float4*)&Ss[j * 68 + d4] = f4_rnd(*(const float4*)&vg[j * 64 + d4]);
    }
    __syncthreads();
    {
        int d = tid >> 2, jj = tid & 3;
        for (int j = jj; j < NKC; j += 4)
            Vt[d * VW + p8(j)] = Ss[j * 68 + d];
        Vt[d * VW + p8(196 + jj)] = 0.f;
    }

    for (int qc = 0; qc < 4; qc++) {
        const int rows = (qc == 3) ? (NKC - 192) : 64;

        for (int u = tid; u < 512; u += 256) {
            int r = u >> 3, g = u & 7;
            float4 v0 = make_float4(0.f, 0.f, 0.f, 0.f), v1 = v0;
            if (r < rows) {
                const float* qp = &g_q[((size_t)bh * NQ + 1 + qc * 64 + r) * 64 + g * 8];
                v0 = f4_rnd(*(const float4*)qp);
                v1 = f4_rnd(*(const float4*)(qp + 4));
            }
            sts_pair8(&Qs[r * QW + g * 8], v0, v1);
        }
        __syncthreads();

        // ---- S = Q @ K^T
        {
            const int wm = warp & 1, wn = warp >> 1;
            float acc[2][7][4];
#pragma unroll
            for (int mt = 0; mt < 2; mt++)
#pragma unroll
                for (int nt = 0; nt < 7; nt++)
#pragma unroll
                    for (int c = 0; c < 4; c++) acc[mt][nt][c] = 0.f;

#pragma unroll
            for (int ks = 0; ks < 8; ks++) {
                const int ko = ks * 8 + 2 * tig;
                uint32_t af[2][4];
#pragma unroll
                for (int mt = 0; mt < 2; mt++) {
                    int r = wm * 32 + mt * 16 + group;
                    float2 lo = *(const float2*)&Qs[r * QW + ko];
                    float2 hi = *(const float2*)&Qs[(r + 8) * QW + ko];
                    af[mt][0] = __float_as_uint(lo.x);
                    af[mt][1] = __float_as_uint(hi.x);
                    af[mt][2] = __float_as_uint(lo.y);
                    af[mt][3] = __float_as_uint(hi.y);
                }
#pragma unroll
                for (int nt = 0; nt < 7; nt++) {
                    int n = wn * 56 + nt * 8 + group;
                    float2 b = *(const float2*)&Ks[n * KW + ko];
                    uint32_t bf[2] = { __float_as_uint(b.x), __float_as_uint(b.y) };
                    mma_tf32(acc[0][nt], af[0], bf);
                    mma_tf32(acc[1][nt], af[1], bf);
                }
            }
#pragma unroll
            for (int mt = 0; mt < 2; mt++) {
                int r = wm * 32 + mt * 16 + group;
#pragma unroll
                for (int nt = 0; nt < 7; nt++) {
                    int n = wn * 56 + nt * 8 + tig * 2;
                    *(float2*)&Ss[r * SW + n]       = make_float2(acc[mt][nt][0], acc[mt][nt][1]);
                    *(float2*)&Ss[(r + 8) * SW + n] = make_float2(acc[mt][nt][2], acc[mt][nt][3]);
                }
            }
        }
        __syncthreads();

        // ---- softmax: ILP-batched
        {
            float mx[8], sum[8];
#pragma unroll
            for (int rr = 0; rr < 8; rr++) mx[rr] = -1e30f;
#pragma unroll
            for (int it = 0; it < 7; it++) {
                int j = lane + it * 32;
                if (j < NKC) {
#pragma unroll
                    for (int rr = 0; rr < 8; rr++)
                        mx[rr] = fmaxf(mx[rr], Ss[(warp * 8 + rr) * SW + j]);
                }
            }
#pragma unroll
            for (int o = 16; o > 0; o >>= 1)
#pragma unroll
                for (int rr = 0; rr < 8; rr++)
                    mx[rr] = fmaxf(mx[rr], __shfl_xor_sync(0xffffffffu, mx[rr], o));
#pragma unroll
            for (int rr = 0; rr < 8; rr++) sum[rr] = 0.f;
#pragma unroll
            for (int it = 0; it < 7; it++) {
                int j = lane + it * 32;
                if (j < NKC) {
#pragma unroll
                    for (int rr = 0; rr < 8; rr++) {
                        float* sp = &Ss[(warp * 8 + rr) * SW + j];
                        float e = fast_exp(*sp - mx[rr]);
                        *sp = rnd_tf32(e);
                        sum[rr] += e;
                    }
                }
            }
#pragma unroll
            for (int o = 16; o > 0; o >>= 1)
#pragma unroll
                for (int rr = 0; rr < 8; rr++)
                    sum[rr] += __shfl_xor_sync(0xffffffffu, sum[rr], o);
            if (lane == 0) {
#pragma unroll
                for (int rr = 0; rr < 8; rr++) Iv[warp * 8 + rr] = 1.f / sum[rr];
            }
        }
        __syncthreads();

        // ---- O = P @ V
        {
            const int wm = warp & 1, wn = warp >> 1;
            float acc[2][2][4];
#pragma unroll
            for (int mt = 0; mt < 2; mt++)
#pragma unroll
                for (int nt = 0; nt < 2; nt++)
#pragma unroll
                    for (int c = 0; c < 4; c++) acc[mt][nt][c] = 0.f;

            for (int ks = 0; ks < 25; ks++) {
                const int kc = ks * 8 + tig;
                const int ko = ks * 8 + 2 * tig;
                uint32_t af[2][4];
#pragma unroll
                for (int mt = 0; mt < 2; mt++) {
                    int r = wm * 32 + mt * 16 + group;
                    af[mt][0] = __float_as_uint(Ss[r * SW + kc]);
                    af[mt][1] = __float_as_uint(Ss[(r + 8) * SW + kc]);
                    af[mt][2] = __float_as_uint(Ss[r * SW + kc + 4]);
                    af[mt][3] = __float_as_uint(Ss[(r + 8) * SW + kc + 4]);
                }
#pragma unroll
                for (int nt = 0; nt < 2; nt++) {
                    int n = wn * 16 + nt * 8 + group;
                    float2 b = *(const float2*)&Vt[n * VW + ko];
                    uint32_t bf[2] = { __float_as_uint(b.x), __float_as_uint(b.y) };
                    mma_tf32(acc[0][nt], af[0], bf);
                    mma_tf32(acc[1][nt], af[1], bf);
                }
            }
#pragma unroll
            for (int mt = 0; mt < 2; mt++) {
#pragma unroll
                for (int half = 0; half < 2; half++) {
                    int rl = wm * 32 + mt * 16 + group + half * 8;
                    int qrow = qc * 64 + rl;
                    if (qrow >= NKC) continue;
                    float iv = Iv[rl];
                    size_t base = ((size_t)bh * NOUT + 1 + (size_t)f * NKC + qrow) * 64;
#pragma unroll
                    for (int nt = 0; nt < 2; nt++) {
                        int col = (warp >> 1) * 16 + nt * 8 + tig * 2;
                        float2 w = make_float2(acc[mt][nt][half * 2] * iv,
                                               acc[mt][nt][half * 2 + 1] * iv);
                        *(float2*)&g_att[base + col] = w;
                    }
                }
            }
        }
        __syncthreads();
    }
}

// ======================= launch =======================
extern "C" void kernel_launch(void* const* d_in, const int* in_sizes, int n_in,
                              void* d_out, int out_size)
{
    const float* x        = (const float*)d_in[0];
    const float* question = (const float*)d_in[1];
    const float* Wq       = (const float*)d_in[2];
    const float* Wkv      = (const float*)d_in[3];
    const float* Wproj    = (const float*)d_in[4];
    const float* bproj    = (const float*)d_in[5];
    float* out = (float*)d_out;

    constexpr int GEMM_SMEM01 = STAGES * (128 * 24 + 128 * 24) * 4;   // 98304
    constexpr int GEMM_SMEM2  = STAGES * (128 * 20 + 128 * 24) * 4;   // 90112

    cudaFuncSetAttribute(fine_attn, cudaFuncAttributeMaxDynamicSharedMemorySize, FINE_SMEM);
    cudaFuncSetAttribute(gemm_tc<0>, cudaFuncAttributeMaxDynamicSharedMemorySize, GEMM_SMEM01);
    cudaFuncSetAttribute(gemm_tc<1>, cudaFuncAttributeMaxDynamicSharedMemorySize, GEMM_SMEM01);
    cudaFuncSetAttribute(gemm_tc<2>, cudaFuncAttributeMaxDynamicSharedMemorySize, GEMM_SMEM2);

    // weight prep + A permutes
    transposeW<<<dim3(768 / 32, 768 / 32), 256>>>(Wq, 0, 768, 768);
    transposeW<<<dim3(1536 / 32, 768 / 32), 256>>>(Wkv, 1, 768, 1536);
    transposeW<<<dim3(768 / 32, 768 / 32), 256>>>(Wproj, 2, 768, 768);

    float* qI; cudaGetSymbolAddress((void**)&qI, g_qI);
    float* xI; cudaGetSymbolAddress((void**)&xI, g_xI);
    {
        int gq = BB * NQ * (KDIM / 8);
        int gx = BB * NV * (KDIM / 8);
        permuteA<<<(gq + 255) / 256, 256>>>(question, qI, gq, 0.125f);
        permuteA<<<(gx + 255) / 256, 256>>>(x, xI, gx, 1.0f);
    }

    gemm_tc<0><<<dim3(768 / BN, (BB * NQ + BM - 1) / BM), 256, GEMM_SMEM01>>>(
        qI, nullptr, nullptr, BB * NQ);

    gemm_tc<1><<<dim3(1536 / BN, (BB * NV) / BM), 256, GEMM_SMEM01>>>(
        xI, nullptr, nullptr, BB * NV);

    cls_attn<<<BHN, 256>>>();
    fine_attn<<<BHN * FF, 256, FINE_SMEM>>>();

    gemm_tc<2><<<dim3(768 / BN, (BB * NOUT + BM - 1) / BM), 256, GEMM_SMEM2>>>(
        nullptr, bproj, out, BB * NOUT);
}

// round 10
// speedup vs baseline: 1.1276x; 1.1276x over previous
#include <cuda_runtime.h>
#include <cstdint>
#include <math.h>

// Problem constants
#define BB    32
#define NQ    197
#define NV    1568
#define DIMD  768
#define HH    12
#define FF    8
#define NKC   196
#define NOUT  1569
#define BHN   384
#define KDIM  768

// ---------------- scratch (device globals) ----------------
__device__ float g_q[(size_t)BHN * NQ * 64];
__device__ float g_k[(size_t)BHN * NV * 64];
__device__ float g_v[(size_t)BHN * NV * 64];
__device__ float g_att[(size_t)BHN * NOUT * 64];
__device__ float g_wqT[768 * 768];      // pair-interleaved [N][K], tf32-rounded
__device__ float g_wkvT[1536 * 768];
__device__ float g_wpT[768 * 768];

// ======================= helpers =======================
__device__ __forceinline__ uint32_t smem_to_u32(const void* p) {
    uint32_t a;
    asm("{ .reg .u64 t; cvta.to.shared.u64 t, %1; cvt.u32.u64 %0, t; }" : "=r"(a) : "l"(p));
    return a;
}
__device__ __forceinline__ uint32_t to_tf32_rn(float x) {
    uint32_t r;
    asm("cvt.rn.tf32.f32 %0, %1;" : "=r"(r) : "f"(x));
    return r;
}
__device__ __forceinline__ float rnd_tf32(float x) { return __uint_as_float(to_tf32_rn(x)); }
__device__ __forceinline__ float4 f4_rnd(float4 v) {
    v.x = rnd_tf32(v.x); v.y = rnd_tf32(v.y); v.z = rnd_tf32(v.z); v.w = rnd_tf32(v.w);
    return v;
}
// pair-interleave position within 8-k groups: [k0,k4,k1,k5,k2,k6,k3,k7]
__device__ __forceinline__ int p8(int k) { return (k & ~7) | ((k & 3) << 1) | ((k >> 2) & 1); }
__device__ __forceinline__ void sts_pair8(float* dst, float4 v0, float4 v1) {
    *(float4*)dst       = make_float4(v0.x, v1.x, v0.y, v1.y);
    *(float4*)(dst + 4) = make_float4(v0.z, v1.z, v0.w, v1.w);
}
__device__ __forceinline__ void cp_async16(uint32_t smem_addr, const void* gptr) {
    asm volatile("cp.async.cg.shared.global [%0], [%1], 16;"
                 :: "r"(smem_addr), "l"(gptr));
}
__device__ __forceinline__ void cp_async16p(uint32_t smem_addr, const void* gptr, bool pred) {
    int sz = pred ? 16 : 0;
    asm volatile("cp.async.cg.shared.global [%0], [%1], 16, %2;"
                 :: "r"(smem_addr), "l"(gptr), "r"(sz));
}
#define CP_COMMIT() asm volatile("cp.async.commit_group;" ::: "memory")
#define CP_WAIT(n)  asm volatile("cp.async.wait_group %0;" :: "n"(n) : "memory")

__device__ __forceinline__ void mma_tf32(float* c, const uint32_t* a, const uint32_t* b) {
    asm volatile(
        "mma.sync.aligned.m16n8k8.row.col.f32.tf32.tf32.f32 "
        "{%0,%1,%2,%3}, {%4,%5,%6,%7}, {%8,%9}, {%0,%1,%2,%3};"
        : "+f"(c[0]), "+f"(c[1]), "+f"(c[2]), "+f"(c[3])
        : "r"(a[0]), "r"(a[1]), "r"(a[2]), "r"(a[3]), "r"(b[0]), "r"(b[1]));
}

// FMA-pipe exp
__device__ __forceinline__ float fast_exp(float x) {
    x = fmaxf(x, -87.0f);
    float y = x * 1.4426950408889634f;
    float r = y + 12582912.0f;
    int   n = __float_as_int(r) - 0x4B400000;
    float f = y - (r - 12582912.0f);
    float p = 1.3333558146e-3f;
    p = fmaf(p, f, 9.6181291076e-3f);
    p = fmaf(p, f, 5.5504108664e-2f);
    p = fmaf(p, f, 2.4022650696e-1f);
    p = fmaf(p, f, 6.9314718056e-1f);
    p = fmaf(p, f, 1.0f);
    return __int_as_float(__float_as_int(p) + (n << 23));
}

// ======================= weight transpose + tf32 round + pair-interleave =======================
__global__ __launch_bounds__(256)
void transposeW(const float* __restrict__ src, int which, int K, int N)
{
    float* dst = (which == 0) ? g_wqT : (which == 1) ? g_wkvT : g_wpT;
    __shared__ float t[32][33];
    int bx = blockIdx.x * 32;   // N block
    int by = blockIdx.y * 32;   // K block
    int txl = threadIdx.x & 31;
    int tyl = threadIdx.x >> 5;
#pragma unroll
    for (int j = 0; j < 32; j += 8)
        t[tyl + j][txl] = src[(size_t)(by + tyl + j) * N + bx + txl];
    __syncthreads();
#pragma unroll
    for (int j = 0; j < 32; j += 8)
        dst[(size_t)(bx + tyl + j) * K + by + p8(txl)] = rnd_tf32(t[txl][tyl + j]);
}

// ======================= mma.sync tf32 GEMM (exact R6) =======================
// A: cp.async natural layout (stride 36), CVT at fragment load.
// B: cp.async raw copy of pre-interleaved weights (stride 40), LDS.64 fragments.
constexpr int BM = 128, BN = 128, BK = 32;
constexpr int SKA = 36;
constexpr int SKB = 40;
constexpr int A_WORDS = BM * SKA;               // 4608
constexpr int B_WORDS = BN * SKB;               // 5120
constexpr int STAGE_WORDS = A_WORDS + B_WORDS;  // 9728
constexpr int GEMM_SMEM = 2 * STAGE_WORDS * 4;  // 77824 bytes
constexpr int KT = KDIM / BK;                   // 24

template<int MODE>
__global__ __launch_bounds__(256, 2)
void gemm_tc(const float* __restrict__ A, const float* __restrict__ bias,
             float* __restrict__ Cout, int M)
{
    extern __shared__ float sm[];
    const uint32_t sb32 = smem_to_u32(sm);
    const int tid   = threadIdx.x;
    const int warp  = tid >> 5;
    const int lane  = tid & 31;
    const int group = lane >> 2;
    const int tig   = lane & 3;
    const int wm    = warp & 3;
    const int wn    = warp >> 2;
    const int row0  = blockIdx.y * BM;
    const int col0  = blockIdx.x * BN;

    const float* BT = (MODE == 0) ? g_wqT : (MODE == 1) ? g_wkvT : g_wpT;

    float acc[2][8][4];
#pragma unroll
    for (int mt = 0; mt < 2; mt++)
#pragma unroll
        for (int nt = 0; nt < 8; nt++)
#pragma unroll
            for (int c = 0; c < 4; c++) acc[mt][nt][c] = 0.f;

    const int lr  = tid >> 3;          // 0..31
    const int lk4 = (tid & 7) << 2;    // 0,4,...,28

    auto load_stage = [&](int kt, int s) {
        const uint32_t aoff = sb32 + (uint32_t)(s * STAGE_WORDS) * 4;
        const uint32_t boff = sb32 + (uint32_t)(s * STAGE_WORDS + A_WORDS) * 4;
        const int k0 = kt * BK;
#pragma unroll
        for (int it = 0; it < 4; it++) {
            int r = lr + it * 32;
            int grow = row0 + r;
            bool ok = grow < M;
            int gr = ok ? grow : 0;
            const float* src;
            if (MODE == 2) {
                int b_ = gr / NOUT;
                int n_ = gr - b_ * NOUT;
                int kk = k0 + lk4;
                int h = kk >> 6, dd = kk & 63;
                src = &g_att[(((size_t)(b_ * HH + h) * NOUT + n_) << 6) + dd];
            } else {
                src = &A[(size_t)gr * KDIM + k0 + lk4];
            }
            cp_async16p(aoff + (uint32_t)(r * SKA + lk4) * 4, src, ok);
        }
#pragma unroll
        for (int it = 0; it < 4; it++) {
            int r = lr + it * 32;
            cp_async16(boff + (uint32_t)(r * SKB + lk4) * 4,
                       &BT[(size_t)(col0 + r) * KDIM + k0 + lk4]);
        }
        CP_COMMIT();
    };

    load_stage(0, 0);

    for (int kt = 0; kt < KT; kt++) {
        const int cur = kt & 1;
        if (kt + 1 < KT) {
            load_stage(kt + 1, (kt + 1) & 1);
            CP_WAIT(1);
        } else {
            CP_WAIT(0);
        }
        __syncthreads();

        const float* As = sm + cur * STAGE_WORDS;
        const float* Bs = As + A_WORDS;

#pragma unroll
        for (int ks = 0; ks < 4; ks++) {
            const int kc = ks * 8 + tig;        // natural k (A)
            const int ko = ks * 8 + 2 * tig;    // interleaved k (B)
            uint32_t af[2][4];
#pragma unroll
            for (int mt = 0; mt < 2; mt++) {
                int r = wm * 32 + mt * 16 + group;
                af[mt][0] = to_tf32_rn(As[r * SKA + kc]);
                af[mt][1] = to_tf32_rn(As[(r + 8) * SKA + kc]);
                af[mt][2] = to_tf32_rn(As[r * SKA + kc + 4]);
                af[mt][3] = to_tf32_rn(As[(r + 8) * SKA + kc + 4]);
            }
#pragma unroll
            for (int nt = 0; nt < 8; nt++) {
                int n = wn * 64 + nt * 8 + group;
                float2 b = *(const float2*)&Bs[n * SKB + ko];
                uint32_t bf[2] = { __float_as_uint(b.x), __float_as_uint(b.y) };
                mma_tf32(acc[0][nt], af[0], bf);
                mma_tf32(acc[1][nt], af[1], bf);
            }
        }
        __syncthreads();
    }

    // ---- epilogue
#pragma unroll
    for (int mt = 0; mt < 2; mt++) {
#pragma unroll
        for (int half = 0; half < 2; half++) {
            int row = row0 + wm * 32 + mt * 16 + group + half * 8;
            if (row >= M) continue;
            int b_, n_;
            if (MODE == 0) { b_ = row / NQ;   n_ = row - b_ * NQ; }
            else if (MODE == 1) { b_ = row / NV; n_ = row - b_ * NV; }
            else { b_ = 0; n_ = 0; }
#pragma unroll
            for (int nt = 0; nt < 8; nt++) {
                int col = col0 + wn * 64 + nt * 8 + tig * 2;
                float v0 = acc[mt][nt][half * 2 + 0];
                float v1 = acc[mt][nt][half * 2 + 1];
                if (MODE == 0) {
                    int h = col >> 6, dd = col & 63;
                    float2 w = make_float2(v0 * 0.125f, v1 * 0.125f);
                    *(float2*)&g_q[(((size_t)(b_ * HH + h) * NQ + n_) << 6) + dd] = w;
                } else if (MODE == 1) {
                    float2 w = make_float2(v0, v1);
                    if (col < DIMD) {
                        int h = col >> 6, dd = col & 63;
                        *(float2*)&g_k[(((size_t)(b_ * HH + h) * NV + n_) << 6) + dd] = w;
                    } else {
                        int c2 = col - DIMD;
                        int h = c2 >> 6, dd = c2 & 63;
                        *(float2*)&g_v[(((size_t)(b_ * HH + h) * NV + n_) << 6) + dd] = w;
                    }
                } else {
                    float2 w = make_float2(v0 + bias[col], v1 + bias[col + 1]);
                    *(float2*)&Cout[(size_t)row * DIMD + col] = w;
                }
            }
        }
    }
}

// ======================= cls-token attention (R6) =======================
__global__ __launch_bounds__(256)
void cls_attn()
{
    __shared__ float qsh[64];
    __shared__ float ssh[NV];
    __shared__ float red[40];
    __shared__ float osh[4][64];

    const int bh   = blockIdx.x;
    const int tid  = threadIdx.x;
    const int lane = tid & 31;
    const int warp = tid >> 5;

    if (tid < 64) qsh[tid] = g_q[((size_t)bh * NQ) * 64 + tid];
    __syncthreads();

    for (int j = warp; j < NV; j += 8) {
        const float* kr = &g_k[((size_t)bh * NV + j) * 64];
        float p = qsh[lane] * kr[lane] + qsh[lane + 32] * kr[lane + 32];
#pragma unroll
        for (int o = 16; o > 0; o >>= 1) p += __shfl_xor_sync(0xffffffffu, p, o);
        if (lane == 0) ssh[j] = p;
    }
    __syncthreads();

    float m = -1e30f;
    for (int j = tid; j < NV; j += 256) m = fmaxf(m, ssh[j]);
#pragma unroll
    for (int o = 16; o > 0; o >>= 1) m = fmaxf(m, __shfl_xor_sync(0xffffffffu, m, o));
    if (lane == 0) red[warp] = m;
    __syncthreads();
    if (tid == 0) {
        float mm = red[0];
        for (int w = 1; w < 8; w++) mm = fmaxf(mm, red[w]);
        red[32] = mm;
    }
    __syncthreads();
    m = red[32];

    float s = 0.f;
    for (int j = tid; j < NV; j += 256) {
        float e = fast_exp(ssh[j] - m);
        ssh[j] = e;
        s += e;
    }
#pragma unroll
    for (int o = 16; o > 0; o >>= 1) s += __shfl_xor_sync(0xffffffffu, s, o);
    if (lane == 0) red[8 + warp] = s;
    __syncthreads();
    if (tid == 0) {
        float ss = 0.f;
        for (int w = 0; w < 8; w++) ss += red[8 + w];
        red[33] = 1.f / ss;
    }
    __syncthreads();
    const float inv = red[33];

    const int g = tid >> 6, dd = tid & 63;
    float o = 0.f;
    for (int j = g; j < NV; j += 4)
        o = fmaf(ssh[j], g_v[((size_t)bh * NV + j) * 64 + dd], o);
    osh[g][dd] = o;
    __syncthreads();
    if (tid < 64) {
        float r = (osh[0][tid] + osh[1][tid] + osh[2][tid] + osh[3][tid]) * inv;
        g_att[((size_t)bh * NOUT) * 64 + tid] = r;
    }
}

// ======================= fine attention — 512 threads (16 warps) =======================
constexpr int QW = 72;    // Qs [64][72]  pair-interleaved d
constexpr int KW = 72;    // Ks [224][72] pair-interleaved d
constexpr int VW = 200;   // Vt [64][200] pair-interleaved keys
constexpr int SW = 228;   // Ss [64][228] natural
constexpr int Q_OFF = 0;
constexpr int K_OFF = Q_OFF + 64 * QW;
constexpr int V_OFF = K_OFF + 224 * KW;
constexpr int S_OFF = V_OFF + 64 * VW;
constexpr int I_OFF = S_OFF + 64 * SW;
constexpr int FINE_SMEM = (I_OFF + 64) * 4;

__global__ __launch_bounds__(512, 1)
void fine_attn()
{
    extern __shared__ float smf[];
    float* Qs = smf + Q_OFF;
    float* Ks = smf + K_OFF;
    float* Vt = smf + V_OFF;
    float* Ss = smf + S_OFF;
    float* Iv = smf + I_OFF;

    const int bh    = blockIdx.x >> 3;
    const int f     = blockIdx.x & 7;
    const int tid   = threadIdx.x;
    const int warp  = tid >> 5;      // 0..15
    const int lane  = tid & 31;
    const int group = lane >> 2;
    const int tig   = lane & 3;
    const int wm    = warp & 3;      // 4 M groups
    const int wn    = warp >> 2;     // 4 N groups

    const float* kg = &g_k[((size_t)bh * NV + (size_t)f * NKC) * 64];
    const float* vg = &g_v[((size_t)bh * NV + (size_t)f * NKC) * 64];

    // ---- K: 224 rows x 8 groups, pair-interleaved + rounded (pad rows zero)
    for (int u = tid; u < 224 * 8; u += 512) {
        int r = u >> 3, g = u & 7;
        float4 v0 = make_float4(0.f, 0.f, 0.f, 0.f), v1 = v0;
        if (r < NKC) {
            v0 = f4_rnd(*(const float4*)&kg[r * 64 + g * 8]);
            v1 = f4_rnd(*(const float4*)&kg[r * 64 + g * 8 + 4]);
        }
        sts_pair8(&Ks[r * KW + g * 8], v0, v1);
    }
    // ---- stage V natural into Ss region [196][68], rounded
    for (int idx = tid; idx < NKC * 16; idx += 512) {
        int j = idx >> 4, d4 = (idx & 15) << 2;
        *(float4*)&Ss[j * 68 + d4] = f4_rnd(*(const float4*)&vg[j * 64 + d4]);
    }
    __syncthreads();
    // ---- transpose -> Vt (pair-interleaved keys), pad keys 196..199 zero
    {
        int d = tid >> 3, jj = tid & 7;
        for (int j = jj; j < NKC; j += 8)
            Vt[d * VW + p8(j)] = Ss[j * 68 + d];
        if (jj < 4) Vt[d * VW + p8(196 + jj)] = 0.f;
    }
    // (sync below, after Q load, orders transpose reads before S-phase writes)

    for (int qc = 0; qc < 4; qc++) {
        const int rows = (qc == 3) ? (NKC - 192) : 64;

        // ---- Q chunk: 64 rows x 8 groups (512 units, one per thread)
        {
            int r = tid >> 3, g = tid & 7;
            float4 v0 = make_float4(0.f, 0.f, 0.f, 0.f), v1 = v0;
            if (r < rows) {
                const float* qp = &g_q[((size_t)bh * NQ + 1 + qc * 64 + r) * 64 + g * 8];
                v0 = f4_rnd(*(const float4*)qp);
                v1 = f4_rnd(*(const float4*)(qp + 4));
            }
            sts_pair8(&Qs[r * QW + g * 8], v0, v1);
        }
        __syncthreads();

        // ---- S = Q @ K^T : warps 4M x 4N, warp tile 16 x 56
        {
            float acc[7][4];
#pragma unroll
            for (int nt = 0; nt < 7; nt++)
#pragma unroll
                for (int c = 0; c < 4; c++) acc[nt][c] = 0.f;

#pragma unroll
            for (int ks = 0; ks < 8; ks++) {
                const int ko = ks * 8 + 2 * tig;
                const int r = wm * 16 + group;
                float2 lo = *(const float2*)&Qs[r * QW + ko];
                float2 hi = *(const float2*)&Qs[(r + 8) * QW + ko];
                uint32_t af[4] = { __float_as_uint(lo.x), __float_as_uint(hi.x),
                                   __float_as_uint(lo.y), __float_as_uint(hi.y) };
#pragma unroll
                for (int nt = 0; nt < 7; nt++) {
                    int n = wn * 56 + nt * 8 + group;
                    float2 b = *(const float2*)&Ks[n * KW + ko];
                    uint32_t bf[2] = { __float_as_uint(b.x), __float_as_uint(b.y) };
                    mma_tf32(acc[nt], af, bf);
                }
            }
            const int r = wm * 16 + group;
#pragma unroll
            for (int nt = 0; nt < 7; nt++) {
                int n = wn * 56 + nt * 8 + tig * 2;
                *(float2*)&Ss[r * SW + n]       = make_float2(acc[nt][0], acc[nt][1]);
                *(float2*)&Ss[(r + 8) * SW + n] = make_float2(acc[nt][2], acc[nt][3]);
            }
        }
        __syncthreads();

        // ---- softmax: 4 rows per warp, ILP-batched; normalization deferred
        {
            float mx[4], sum[4];
#pragma unroll
            for (int rr = 0; rr < 4; rr++) mx[rr] = -1e30f;
#pragma unroll
            for (int it = 0; it < 7; it++) {
                int j = lane + it * 32;
                if (j < NKC) {
#pragma unroll
                    for (int rr = 0; rr < 4; rr++)
                        mx[rr] = fmaxf(mx[rr], Ss[(warp * 4 + rr) * SW + j]);
                }
            }
#pragma unroll
            for (int o = 16; o > 0; o >>= 1)
#pragma unroll
                for (int rr = 0; rr < 4; rr++)
                    mx[rr] = fmaxf(mx[rr], __shfl_xor_sync(0xffffffffu, mx[rr], o));
#pragma unroll
            for (int rr = 0; rr < 4; rr++) sum[rr] = 0.f;
#pragma unroll
            for (int it = 0; it < 7; it++) {
                int j = lane + it * 32;
                if (j < NKC) {
#pragma unroll
                    for (int rr = 0; rr < 4; rr++) {
                        float* sp = &Ss[(warp * 4 + rr) * SW + j];
                        float e = fast_exp(*sp - mx[rr]);
                        *sp = rnd_tf32(e);
                        sum[rr] += e;
                    }
                }
            }
#pragma unroll
            for (int o = 16; o > 0; o >>= 1)
#pragma unroll
                for (int rr = 0; rr < 4; rr++)
                    sum[rr] += __shfl_xor_sync(0xffffffffu, sum[rr], o);
            if (lane == 0) {
#pragma unroll
                for (int rr = 0; rr < 4; rr++) Iv[warp * 4 + rr] = 1.f / sum[rr];
            }
        }
        __syncthreads();

        // ---- O = P @ V : warps 4M x 4N, warp tile 16 x 16; k over 200 (pads zero)
        {
            float acc[2][4];
#pragma unroll
            for (int nt = 0; nt < 2; nt++)
#pragma unroll
                for (int c = 0; c < 4; c++) acc[nt][c] = 0.f;

            for (int ks = 0; ks < 25; ks++) {
                const int kc = ks * 8 + tig;       // natural (P in Ss)
                const int ko = ks * 8 + 2 * tig;   // interleaved (Vt)
                const int r = wm * 16 + group;
                uint32_t af[4] = {
                    __float_as_uint(Ss[r * SW + kc]),
                    __float_as_uint(Ss[(r + 8) * SW + kc]),
                    __float_as_uint(Ss[r * SW + kc + 4]),
                    __float_as_uint(Ss[(r + 8) * SW + kc + 4]) };
#pragma unroll
                for (int nt = 0; nt < 2; nt++) {
                    int n = wn * 16 + nt * 8 + group;
                    float2 b = *(const float2*)&Vt[n * VW + ko];
                    uint32_t bf[2] = { __float_as_uint(b.x), __float_as_uint(b.y) };
                    mma_tf32(acc[nt], af, bf);
                }
            }
#pragma unroll
            for (int half = 0; half < 2; half++) {
                int rl = wm * 16 + group + half * 8;
                int qrow = qc * 64 + rl;
                if (qrow >= NKC) continue;
                float iv = Iv[rl];
                size_t base = ((size_t)bh * NOUT + 1 + (size_t)f * NKC + qrow) * 64;
#pragma unroll
                for (int nt = 0; nt < 2; nt++) {
                    int col = wn * 16 + nt * 8 + tig * 2;
                    float2 w = make_float2(acc[nt][half * 2] * iv,
                                           acc[nt][half * 2 + 1] * iv);
                    *(float2*)&g_att[base + col] = w;
                }
            }
        }
        __syncthreads();
    }
}

// ======================= launch =======================
extern "C" void kernel_launch(void* const* d_in, const int* in_sizes, int n_in,
                              void* d_out, int out_size)
{
    const float* x        = (const float*)d_in[0];
    const float* question = (const float*)d_in[1];
    const float* Wq       = (const float*)d_in[2];
    const float* Wkv      = (const float*)d_in[3];
    const float* Wproj    = (const float*)d_in[4];
    const float* bproj    = (const float*)d_in[5];
    float* out = (float*)d_out;

    cudaFuncSetAttribute(fine_attn, cudaFuncAttributeMaxDynamicSharedMemorySize, FINE_SMEM);
    cudaFuncSetAttribute(gemm_tc<0>, cudaFuncAttributeMaxDynamicSharedMemorySize, GEMM_SMEM);
    cudaFuncSetAttribute(gemm_tc<1>, cudaFuncAttributeMaxDynamicSharedMemorySize, GEMM_SMEM);
    cudaFuncSetAttribute(gemm_tc<2>, cudaFuncAttributeMaxDynamicSharedMemorySize, GEMM_SMEM);

    // weight prep
    transposeW<<<dim3(768 / 32, 768 / 32), 256>>>(Wq, 0, 768, 768);
    transposeW<<<dim3(1536 / 32, 768 / 32), 256>>>(Wkv, 1, 768, 1536);
    transposeW<<<dim3(768 / 32, 768 / 32), 256>>>(Wproj, 2, 768, 768);

    gemm_tc<0><<<dim3(768 / BN, (BB * NQ + BM - 1) / BM), 256, GEMM_SMEM>>>(
        question, nullptr, nullptr, BB * NQ);

    gemm_tc<1><<<dim3(1536 / BN, (BB * NV) / BM), 256, GEMM_SMEM>>>(
        x, nullptr, nullptr, BB * NV);

    cls_attn<<<BHN, 256>>>();
    fine_attn<<<BHN * FF, 512, FINE_SMEM>>>();

    gemm_tc<2><<<dim3(768 / BN, (BB * NOUT + BM - 1) / BM), 256, GEMM_SMEM>>>(
        nullptr, bproj, out, BB * NOUT);
}

// round 11
// speedup vs baseline: 1.1421x; 1.0129x over previous
#include <cuda_runtime.h>
#include <cstdint>
#include <math.h>

// Problem constants
#define BB    32
#define NQ    197
#define NV    1568
#define DIMD  768
#define HH    12
#define FF    8
#define NKC   196
#define NOUT  1569
#define BHN   384
#define KDIM  768

// ---------------- scratch (device globals) ----------------
__device__ float g_q[(size_t)BHN * NQ * 64];
__device__ float g_k[(size_t)BHN * NV * 64];
__device__ float g_v[(size_t)BHN * NV * 64];
__device__ float g_att[(size_t)BHN * NOUT * 64];
__device__ float g_wqT[768 * 768];      // pair-interleaved [N][K], tf32-rounded
__device__ float g_wkvT[1536 * 768];
__device__ float g_wpT[768 * 768];

// ======================= helpers =======================
__device__ __forceinline__ uint32_t smem_to_u32(const void* p) {
    uint32_t a;
    asm("{ .reg .u64 t; cvta.to.shared.u64 t, %1; cvt.u32.u64 %0, t; }" : "=r"(a) : "l"(p));
    return a;
}
__device__ __forceinline__ uint32_t to_tf32_rn(float x) {
    uint32_t r;
    asm("cvt.rn.tf32.f32 %0, %1;" : "=r"(r) : "f"(x));
    return r;
}
__device__ __forceinline__ float rnd_tf32(float x) { return __uint_as_float(to_tf32_rn(x)); }
__device__ __forceinline__ float4 f4_rnd(float4 v) {
    v.x = rnd_tf32(v.x); v.y = rnd_tf32(v.y); v.z = rnd_tf32(v.z); v.w = rnd_tf32(v.w);
    return v;
}
// pair-interleave position within 8-k groups: [k0,k4,k1,k5,k2,k6,k3,k7]
__device__ __forceinline__ int p8(int k) { return (k & ~7) | ((k & 3) << 1) | ((k >> 2) & 1); }
__device__ __forceinline__ void sts_pair8(float* dst, float4 v0, float4 v1) {
    *(float4*)dst       = make_float4(v0.x, v1.x, v0.y, v1.y);
    *(float4*)(dst + 4) = make_float4(v0.z, v1.z, v0.w, v1.w);
}
__device__ __forceinline__ void cp_async16(uint32_t smem_addr, const void* gptr) {
    asm volatile("cp.async.cg.shared.global [%0], [%1], 16;"
                 :: "r"(smem_addr), "l"(gptr));
}
__device__ __forceinline__ void cp_async16p(uint32_t smem_addr, const void* gptr, bool pred) {
    int sz = pred ? 16 : 0;
    asm volatile("cp.async.cg.shared.global [%0], [%1], 16, %2;"
                 :: "r"(smem_addr), "l"(gptr), "r"(sz));
}
#define CP_COMMIT() asm volatile("cp.async.commit_group;" ::: "memory")
#define CP_WAIT(n)  asm volatile("cp.async.wait_group %0;" :: "n"(n) : "memory")

__device__ __forceinline__ void mma_tf32(float* c, const uint32_t* a, const uint32_t* b) {
    asm volatile(
        "mma.sync.aligned.m16n8k8.row.col.f32.tf32.tf32.f32 "
        "{%0,%1,%2,%3}, {%4,%5,%6,%7}, {%8,%9}, {%0,%1,%2,%3};"
        : "+f"(c[0]), "+f"(c[1]), "+f"(c[2]), "+f"(c[3])
        : "r"(a[0]), "r"(a[1]), "r"(a[2]), "r"(a[3]), "r"(b[0]), "r"(b[1]));
}

// FMA-pipe exp
__device__ __forceinline__ float fast_exp(float x) {
    x = fmaxf(x, -87.0f);
    float y = x * 1.4426950408889634f;
    float r = y + 12582912.0f;
    int   n = __float_as_int(r) - 0x4B400000;
    float f = y - (r - 12582912.0f);
    float p = 1.3333558146e-3f;
    p = fmaf(p, f, 9.6181291076e-3f);
    p = fmaf(p, f, 5.5504108664e-2f);
    p = fmaf(p, f, 2.4022650696e-1f);
    p = fmaf(p, f, 6.9314718056e-1f);
    p = fmaf(p, f, 1.0f);
    return __int_as_float(__float_as_int(p) + (n << 23));
}

// ======================= weight transpose + tf32 round + pair-interleave =======================
__global__ __launch_bounds__(256)
void transposeW(const float* __restrict__ src, int which, int K, int N)
{
    float* dst = (which == 0) ? g_wqT : (which == 1) ? g_wkvT : g_wpT;
    __shared__ float t[32][33];
    int bx = blockIdx.x * 32;   // N block
    int by = blockIdx.y * 32;   // K block
    int txl = threadIdx.x & 31;
    int tyl = threadIdx.x >> 5;
#pragma unroll
    for (int j = 0; j < 32; j += 8)
        t[tyl + j][txl] = src[(size_t)(by + tyl + j) * N + bx + txl];
    __syncthreads();
#pragma unroll
    for (int j = 0; j < 32; j += 8)
        dst[(size_t)(bx + tyl + j) * K + by + p8(txl)] = rnd_tf32(t[txl][tyl + j]);
}

// ======================= mma.sync tf32 GEMM: BN=96, 3-stage ring, 1 sync/ktile ==========
constexpr int BM = 128, BN = 96, BK = 32;
constexpr int SKA = 36;
constexpr int SKB = 40;
constexpr int A_WORDS = BM * SKA;               // 4608
constexpr int B_WORDS = BN * SKB;               // 3840
constexpr int STAGE_WORDS = A_WORDS + B_WORDS;  // 8448
constexpr int GSTAGES = 3;
constexpr int GEMM_SMEM = GSTAGES * STAGE_WORDS * 4;  // 101376 bytes
constexpr int KT = KDIM / BK;                   // 24

template<int MODE>
__global__ __launch_bounds__(256, 2)
void gemm_tc(const float* __restrict__ A, const float* __restrict__ bias,
             float* __restrict__ Cout, int M)
{
    extern __shared__ float sm[];
    const uint32_t sb32 = smem_to_u32(sm);
    const int tid   = threadIdx.x;
    const int warp  = tid >> 5;
    const int lane  = tid & 31;
    const int group = lane >> 2;
    const int tig   = lane & 3;
    const int wm    = warp & 3;
    const int wn    = warp >> 2;
    const int row0  = blockIdx.y * BM;
    const int col0  = blockIdx.x * BN;

    const float* BT = (MODE == 0) ? g_wqT : (MODE == 1) ? g_wkvT : g_wpT;

    float acc[2][6][4];
#pragma unroll
    for (int mt = 0; mt < 2; mt++)
#pragma unroll
        for (int nt = 0; nt < 6; nt++)
#pragma unroll
            for (int c = 0; c < 4; c++) acc[mt][nt][c] = 0.f;

    const int lr  = tid >> 3;          // 0..31
    const int lk4 = (tid & 7) << 2;    // 0,4,...,28

    auto load_stage = [&](int kt, int s) {
        const uint32_t aoff = sb32 + (uint32_t)(s * STAGE_WORDS) * 4;
        const uint32_t boff = sb32 + (uint32_t)(s * STAGE_WORDS + A_WORDS) * 4;
        const int k0 = kt * BK;
        // A: 128 rows x 8 f4-cols = 1024 f4 -> 4/thread
#pragma unroll
        for (int it = 0; it < 4; it++) {
            int r = lr + it * 32;
            int grow = row0 + r;
            bool ok = grow < M;
            int gr = ok ? grow : 0;
            const float* src;
            if (MODE == 2) {
                int b_ = gr / NOUT;
                int n_ = gr - b_ * NOUT;
                int kk = k0 + lk4;
                int h = kk >> 6, dd = kk & 63;
                src = &g_att[(((size_t)(b_ * HH + h) * NOUT + n_) << 6) + dd];
            } else {
                src = &A[(size_t)gr * KDIM + k0 + lk4];
            }
            cp_async16p(aoff + (uint32_t)(r * SKA + lk4) * 4, src, ok);
        }
        // B: 96 rows x 8 f4-cols = 768 f4 -> 3/thread
#pragma unroll
        for (int it = 0; it < 3; it++) {
            int idx = tid + it * 256;
            int r = idx >> 3, c4 = (idx & 7) << 2;
            cp_async16(boff + (uint32_t)(r * SKB + c4) * 4,
                       &BT[(size_t)(col0 + r) * KDIM + k0 + c4]);
        }
        CP_COMMIT();
    };

    load_stage(0, 0);
    load_stage(1, 1);

    for (int kt = 0; kt < KT; kt++) {
        if (kt + 1 < KT) { CP_WAIT(1); } else { CP_WAIT(0); }
        __syncthreads();
        // safe: stage (kt+2)%3 == (kt-1)%3 was consumed before the sync above
        if (kt + 2 < KT) load_stage(kt + 2, (kt + 2) % GSTAGES);

        const float* As = sm + (kt % GSTAGES) * STAGE_WORDS;
        const float* Bs = As + A_WORDS;

#pragma unroll
        for (int ks = 0; ks < 4; ks++) {
            const int kc = ks * 8 + tig;        // natural k (A)
            const int ko = ks * 8 + 2 * tig;    // interleaved k (B)
            uint32_t af[2][4];
#pragma unroll
            for (int mt = 0; mt < 2; mt++) {
                int r = wm * 32 + mt * 16 + group;
                af[mt][0] = to_tf32_rn(As[r * SKA + kc]);
                af[mt][1] = to_tf32_rn(As[(r + 8) * SKA + kc]);
                af[mt][2] = to_tf32_rn(As[r * SKA + kc + 4]);
                af[mt][3] = to_tf32_rn(As[(r + 8) * SKA + kc + 4]);
            }
#pragma unroll
            for (int nt = 0; nt < 6; nt++) {
                int n = wn * 48 + nt * 8 + group;
                float2 b = *(const float2*)&Bs[n * SKB + ko];
                uint32_t bf[2] = { __float_as_uint(b.x), __float_as_uint(b.y) };
                mma_tf32(acc[0][nt], af[0], bf);
                mma_tf32(acc[1][nt], af[1], bf);
            }
        }
    }

    // ---- epilogue
#pragma unroll
    for (int mt = 0; mt < 2; mt++) {
#pragma unroll
        for (int half = 0; half < 2; half++) {
            int row = row0 + wm * 32 + mt * 16 + group + half * 8;
            if (row >= M) continue;
            int b_, n_;
            if (MODE == 0) { b_ = row / NQ;   n_ = row - b_ * NQ; }
            else if (MODE == 1) { b_ = row / NV; n_ = row - b_ * NV; }
            else { b_ = 0; n_ = 0; }
#pragma unroll
            for (int nt = 0; nt < 6; nt++) {
                int col = col0 + wn * 48 + nt * 8 + tig * 2;
                float v0 = acc[mt][nt][half * 2 + 0];
                float v1 = acc[mt][nt][half * 2 + 1];
                if (MODE == 0) {
                    int h = col >> 6, dd = col & 63;
                    float2 w = make_float2(v0 * 0.125f, v1 * 0.125f);
                    *(float2*)&g_q[(((size_t)(b_ * HH + h) * NQ + n_) << 6) + dd] = w;
                } else if (MODE == 1) {
                    float2 w = make_float2(v0, v1);
                    if (col < DIMD) {
                        int h = col >> 6, dd = col & 63;
                        *(float2*)&g_k[(((size_t)(b_ * HH + h) * NV + n_) << 6) + dd] = w;
                    } else {
                        int c2 = col - DIMD;
                        int h = c2 >> 6, dd = c2 & 63;
                        *(float2*)&g_v[(((size_t)(b_ * HH + h) * NV + n_) << 6) + dd] = w;
                    }
                } else {
                    float2 w = make_float2(v0 + bias[col], v1 + bias[col + 1]);
                    *(float2*)&Cout[(size_t)row * DIMD + col] = w;
                }
            }
        }
    }
}

// ======================= cls-token attention (unchanged) =======================
__global__ __launch_bounds__(256)
void cls_attn()
{
    __shared__ float qsh[64];
    __shared__ float ssh[NV];
    __shared__ float red[40];
    __shared__ float osh[4][64];

    const int bh   = blockIdx.x;
    const int tid  = threadIdx.x;
    const int lane = tid & 31;
    const int warp = tid >> 5;

    if (tid < 64) qsh[tid] = g_q[((size_t)bh * NQ) * 64 + tid];
    __syncthreads();

    for (int j = warp; j < NV; j += 8) {
        const float* kr = &g_k[((size_t)bh * NV + j) * 64];
        float p = qsh[lane] * kr[lane] + qsh[lane + 32] * kr[lane + 32];
#pragma unroll
        for (int o = 16; o > 0; o >>= 1) p += __shfl_xor_sync(0xffffffffu, p, o);
        if (lane == 0) ssh[j] = p;
    }
    __syncthreads();

    float m = -1e30f;
    for (int j = tid; j < NV; j += 256) m = fmaxf(m, ssh[j]);
#pragma unroll
    for (int o = 16; o > 0; o >>= 1) m = fmaxf(m, __shfl_xor_sync(0xffffffffu, m, o));
    if (lane == 0) red[warp] = m;
    __syncthreads();
    if (tid == 0) {
        float mm = red[0];
        for (int w = 1; w < 8; w++) mm = fmaxf(mm, red[w]);
        red[32] = mm;
    }
    __syncthreads();
    m = red[32];

    float s = 0.f;
    for (int j = tid; j < NV; j += 256) {
        float e = fast_exp(ssh[j] - m);
        ssh[j] = e;
        s += e;
    }
#pragma unroll
    for (int o = 16; o > 0; o >>= 1) s += __shfl_xor_sync(0xffffffffu, s, o);
    if (lane == 0) red[8 + warp] = s;
    __syncthreads();
    if (tid == 0) {
        float ss = 0.f;
        for (int w = 0; w < 8; w++) ss += red[8 + w];
        red[33] = 1.f / ss;
    }
    __syncthreads();
    const float inv = red[33];

    const int g = tid >> 6, dd = tid & 63;
    float o = 0.f;
    for (int j = g; j < NV; j += 4)
        o = fmaf(ssh[j], g_v[((size_t)bh * NV + j) * 64 + dd], o);
    osh[g][dd] = o;
    __syncthreads();
    if (tid < 64) {
        float r = (osh[0][tid] + osh[1][tid] + osh[2][tid] + osh[3][tid]) * inv;
        g_att[((size_t)bh * NOUT) * 64 + tid] = r;
    }
}

// ======================= fine attention — 512 thr, natural V, Q double-buffer ===========
constexpr int QWN = 68;   // Q natural [64][68], two buffers
constexpr int KW  = 72;   // Ks [224][72] pair-interleaved d
constexpr int VWN = 72;   // Vn [200][72] natural (rows 196..199 zero)
constexpr int SW  = 228;  // Ss [64][228]
constexpr int Q0_OFF = 0;
constexpr int Q1_OFF = Q0_OFF + 64 * QWN;   // 4352
constexpr int K_OFF  = Q1_OFF + 64 * QWN;   // 8704
constexpr int V_OFF  = K_OFF + 224 * KW;    // 24832
constexpr int S_OFF  = V_OFF + 200 * VWN;   // 39232
constexpr int I_OFF  = S_OFF + 64 * SW;     // 53824
constexpr int FINE_SMEM = (I_OFF + 64) * 4; // 215552 bytes

__global__ __launch_bounds__(512, 1)
void fine_attn()
{
    extern __shared__ float smf[];
    float* Ks = smf + K_OFF;
    float* Vn = smf + V_OFF;
    float* Ss = smf + S_OFF;
    float* Iv = smf + I_OFF;

    const int bh    = blockIdx.x >> 3;
    const int f     = blockIdx.x & 7;
    const int tid   = threadIdx.x;
    const int warp  = tid >> 5;      // 0..15
    const int lane  = tid & 31;
    const int group = lane >> 2;
    const int tig   = lane & 3;
    const int wm    = warp & 3;
    const int wn    = warp >> 2;

    const uint32_t sb32 = smem_to_u32(smf);
    const float* kg = &g_k[((size_t)bh * NV + (size_t)f * NKC) * 64];
    const float* vg = &g_v[((size_t)bh * NV + (size_t)f * NKC) * 64];
    const float* qg = &g_q[((size_t)bh * NQ + 1) * 64];

    // ---- V: raw cp.async into natural [196][72] (cols 64..71 unused)
    for (int idx = tid; idx < NKC * 16; idx += 512) {
        int j = idx >> 4, c4 = (idx & 15) << 2;
        cp_async16(sb32 + (uint32_t)(V_OFF + j * VWN + c4) * 4, &vg[j * 64 + c4]);
    }
    CP_COMMIT();

    auto loadQ = [&](int qc, int buf) {
        const int rows = (qc == 3) ? (NKC - 192) : 64;
        const uint32_t qoff = sb32 + (uint32_t)((buf ? Q1_OFF : Q0_OFF)) * 4;
#pragma unroll
        for (int it = 0; it < 2; it++) {
            int idx = tid + it * 512;
            int r = idx >> 4, c4 = (idx & 15) << 2;
            cp_async16p(qoff + (uint32_t)(r * QWN + c4) * 4,
                        &qg[(size_t)(qc * 64 + r) * 64 + c4], r < rows);
        }
        CP_COMMIT();
    };
    loadQ(0, 0);

    // ---- K: LDG + interleave + round (pad rows 196..223 zero)
    for (int u = tid; u < 224 * 8; u += 512) {
        int r = u >> 3, g = u & 7;
        float4 v0 = make_float4(0.f, 0.f, 0.f, 0.f), v1 = v0;
        if (r < NKC) {
            v0 = f4_rnd(*(const float4*)&kg[r * 64 + g * 8]);
            v1 = f4_rnd(*(const float4*)&kg[r * 64 + g * 8 + 4]);
        }
        sts_pair8(&Ks[r * KW + g * 8], v0, v1);
    }
    // ---- V pad rows 196..199 zero (full 72-word rows)
    for (int idx = tid; idx < 4 * 18; idx += 512) {
        int r = 196 + idx / 18, c4 = (idx % 18) * 4;
        *(float4*)&Vn[r * VWN + c4] = make_float4(0.f, 0.f, 0.f, 0.f);
    }

    for (int qc = 0; qc < 4; qc++) {
        if (qc < 3) loadQ(qc + 1, (qc + 1) & 1);
        if (qc < 3) { CP_WAIT(1); } else { CP_WAIT(0); }
        __syncthreads();

        const float* Qc = smf + ((qc & 1) ? Q1_OFF : Q0_OFF);

        // ---- S = Q @ K^T : warps 4M x 4N, warp tile 16 x 56
        {
            float acc[7][4];
#pragma unroll
            for (int nt = 0; nt < 7; nt++)
#pragma unroll
                for (int c = 0; c < 4; c++) acc[nt][c] = 0.f;

#pragma unroll
            for (int ks = 0; ks < 8; ks++) {
                const int kc = ks * 8 + tig;        // natural (Q)
                const int ko = ks * 8 + 2 * tig;    // interleaved (K)
                const int r = wm * 16 + group;
                uint32_t af[4];
                af[0] = to_tf32_rn(Qc[r * QWN + kc]);
                af[1] = to_tf32_rn(Qc[(r + 8) * QWN + kc]);
                af[2] = to_tf32_rn(Qc[r * QWN + kc + 4]);
                af[3] = to_tf32_rn(Qc[(r + 8) * QWN + kc + 4]);
#pragma unroll
                for (int nt = 0; nt < 7; nt++) {
                    int n = wn * 56 + nt * 8 + group;
                    float2 b = *(const float2*)&Ks[n * KW + ko];
                    uint32_t bf[2] = { __float_as_uint(b.x), __float_as_uint(b.y) };
                    mma_tf32(acc[nt], af, bf);
                }
            }
            const int r = wm * 16 + group;
#pragma unroll
            for (int nt = 0; nt < 7; nt++) {
                int n = wn * 56 + nt * 8 + tig * 2;
                *(float2*)&Ss[r * SW + n]       = make_float2(acc[nt][0], acc[nt][1]);
                *(float2*)&Ss[(r + 8) * SW + n] = make_float2(acc[nt][2], acc[nt][3]);
            }
        }
        __syncthreads();

        // ---- softmax: 4 rows per warp, ILP-batched; normalization deferred
        {
            float mx[4], sum[4];
#pragma unroll
            for (int rr = 0; rr < 4; rr++) mx[rr] = -1e30f;
#pragma unroll
            for (int it = 0; it < 7; it++) {
                int j = lane + it * 32;
                if (j < NKC) {
#pragma unroll
                    for (int rr = 0; rr < 4; rr++)
                        mx[rr] = fmaxf(mx[rr], Ss[(warp * 4 + rr) * SW + j]);
                }
            }
#pragma unroll
            for (int o = 16; o > 0; o >>= 1)
#pragma unroll
                for (int rr = 0; rr < 4; rr++)
                    mx[rr] = fmaxf(mx[rr], __shfl_xor_sync(0xffffffffu, mx[rr], o));
#pragma unroll
            for (int rr = 0; rr < 4; rr++) sum[rr] = 0.f;
#pragma unroll
            for (int it = 0; it < 7; it++) {
                int j = lane + it * 32;
                if (j < NKC) {
#pragma unroll
                    for (int rr = 0; rr < 4; rr++) {
                        float* sp = &Ss[(warp * 4 + rr) * SW + j];
                        float e = fast_exp(*sp - mx[rr]);
                        *sp = rnd_tf32(e);
                        sum[rr] += e;
                    }
                }
            }
#pragma unroll
            for (int o = 16; o > 0; o >>= 1)
#pragma unroll
                for (int rr = 0; rr < 4; rr++)
                    sum[rr] += __shfl_xor_sync(0xffffffffu, sum[rr], o);
            if (lane == 0) {
#pragma unroll
                for (int rr = 0; rr < 4; rr++) Iv[warp * 4 + rr] = 1.f / sum[rr];
            }
        }
        __syncthreads();

        // ---- O = P @ V : warps 4M x 4N, warp tile 16 x 16; V natural (rows 196..199 = 0)
        {
            float acc[2][4];
#pragma unroll
            for (int nt = 0; nt < 2; nt++)
#pragma unroll
                for (int c = 0; c < 4; c++) acc[nt][c] = 0.f;

            for (int ks = 0; ks < 25; ks++) {
                const int kc = ks * 8 + tig;
                const int r = wm * 16 + group;
                uint32_t af[4] = {
                    __float_as_uint(Ss[r * SW + kc]),
                    __float_as_uint(Ss[(r + 8) * SW + kc]),
                    __float_as_uint(Ss[r * SW + kc + 4]),
                    __float_as_uint(Ss[(r + 8) * SW + kc + 4]) };
#pragma unroll
                for (int nt = 0; nt < 2; nt++) {
                    int n = wn * 16 + nt * 8 + group;
                    uint32_t bf[2];
                    bf[0] = to_tf32_rn(Vn[(ks * 8 + tig) * VWN + n]);
                    bf[1] = to_tf32_rn(Vn[(ks * 8 + tig + 4) * VWN + n]);
                    mma_tf32(acc[nt], af, bf);
                }
            }
#pragma unroll
            for (int half = 0; half < 2; half++) {
                int rl = wm * 16 + group + half * 8;
                int qrow = qc * 64 + rl;
                if (qrow >= NKC) continue;
                float iv = Iv[rl];
                size_t base = ((size_t)bh * NOUT + 1 + (size_t)f * NKC + qrow) * 64;
#pragma unroll
                for (int nt = 0; nt < 2; nt++) {
                    int col = wn * 16 + nt * 8 + tig * 2;
                    float2 w = make_float2(acc[nt][half * 2] * iv,
                                           acc[nt][half * 2 + 1] * iv);
                    *(float2*)&g_att[base + col] = w;
                }
            }
        }
        __syncthreads();
    }
}

// ======================= launch =======================
extern "C" void kernel_launch(void* const* d_in, const int* in_sizes, int n_in,
                              void* d_out, int out_size)
{
    const float* x        = (const float*)d_in[0];
    const float* question = (const float*)d_in[1];
    const float* Wq       = (const float*)d_in[2];
    const float* Wkv      = (const float*)d_in[3];
    const float* Wproj    = (const float*)d_in[4];
    const float* bproj    = (const float*)d_in[5];
    float* out = (float*)d_out;

    cudaFuncSetAttribute(fine_attn, cudaFuncAttributeMaxDynamicSharedMemorySize, FINE_SMEM);
    cudaFuncSetAttribute(gemm_tc<0>, cudaFuncAttributeMaxDynamicSharedMemorySize, GEMM_SMEM);
    cudaFuncSetAttribute(gemm_tc<1>, cudaFuncAttributeMaxDynamicSharedMemorySize, GEMM_SMEM);
    cudaFuncSetAttribute(gemm_tc<2>, cudaFuncAttributeMaxDynamicSharedMemorySize, GEMM_SMEM);

    // weight prep
    transposeW<<<dim3(768 / 32, 768 / 32), 256>>>(Wq, 0, 768, 768);
    transposeW<<<dim3(1536 / 32, 768 / 32), 256>>>(Wkv, 1, 768, 1536);
    transposeW<<<dim3(768 / 32, 768 / 32), 256>>>(Wproj, 2, 768, 768);

    gemm_tc<0><<<dim3(768 / BN, (BB * NQ + BM - 1) / BM), 256, GEMM_SMEM>>>(
        question, nullptr, nullptr, BB * NQ);

    gemm_tc<1><<<dim3(1536 / BN, (BB * NV) / BM), 256, GEMM_SMEM>>>(
        x, nullptr, nullptr, BB * NV);

    cls_attn<<<BHN, 256>>>();
    fine_attn<<<BHN * FF, 512, FINE_SMEM>>>();

    gemm_tc<2><<<dim3(768 / BN, (BB * NOUT + BM - 1) / BM), 256, GEMM_SMEM>>>(
        nullptr, bproj, out, BB * NOUT);
}

// round 12
// speedup vs baseline: 1.1934x; 1.0449x over previous
#include <cuda_runtime.h>
#include <cstdint>
#include <math.h>

// Problem constants
#define BB    32
#define NQ    197
#define NV    1568
#define DIMD  768
#define HH    12
#define FF    8
#define NKC   196
#define NOUT  1569
#define BHN   384
#define KDIM  768

// ---------------- scratch (device globals) ----------------
__device__ float g_q[(size_t)BHN * NQ * 64];
__device__ float g_k[(size_t)BHN * NV * 64];
__device__ float g_v[(size_t)BHN * NV * 64];
__device__ float g_att[(size_t)BHN * NOUT * 64];
__device__ float g_wqT[768 * 768];      // pair-interleaved [N][K], tf32-rounded
__device__ float g_wkvT[1536 * 768];
__device__ float g_wpT[768 * 768];

// ======================= helpers =======================
__device__ __forceinline__ uint32_t smem_to_u32(const void* p) {
    uint32_t a;
    asm("{ .reg .u64 t; cvta.to.shared.u64 t, %1; cvt.u32.u64 %0, t; }" : "=r"(a) : "l"(p));
    return a;
}
__device__ __forceinline__ uint32_t to_tf32_rn(float x) {
    uint32_t r;
    asm("cvt.rn.tf32.f32 %0, %1;" : "=r"(r) : "f"(x));
    return r;
}
__device__ __forceinline__ float rnd_tf32(float x) { return __uint_as_float(to_tf32_rn(x)); }
__device__ __forceinline__ float4 f4_rnd(float4 v) {
    v.x = rnd_tf32(v.x); v.y = rnd_tf32(v.y); v.z = rnd_tf32(v.z); v.w = rnd_tf32(v.w);
    return v;
}
// pair-interleave position within 8-k groups: [k0,k4,k1,k5,k2,k6,k3,k7]
__device__ __forceinline__ int p8(int k) { return (k & ~7) | ((k & 3) << 1) | ((k >> 2) & 1); }
__device__ __forceinline__ void sts_pair8(float* dst, float4 v0, float4 v1) {
    *(float4*)dst       = make_float4(v0.x, v1.x, v0.y, v1.y);
    *(float4*)(dst + 4) = make_float4(v0.z, v1.z, v0.w, v1.w);
}
__device__ __forceinline__ void cp_async16(uint32_t smem_addr, const void* gptr) {
    asm volatile("cp.async.cg.shared.global [%0], [%1], 16;"
                 :: "r"(smem_addr), "l"(gptr));
}
__device__ __forceinline__ void cp_async16p(uint32_t smem_addr, const void* gptr, bool pred) {
    int sz = pred ? 16 : 0;
    asm volatile("cp.async.cg.shared.global [%0], [%1], 16, %2;"
                 :: "r"(smem_addr), "l"(gptr), "r"(sz));
}
#define CP_COMMIT() asm volatile("cp.async.commit_group;" ::: "memory")
#define CP_WAIT(n)  asm volatile("cp.async.wait_group %0;" :: "n"(n) : "memory")

__device__ __forceinline__ void mma_tf32(float* c, const uint32_t* a, const uint32_t* b) {
    asm volatile(
        "mma.sync.aligned.m16n8k8.row.col.f32.tf32.tf32.f32 "
        "{%0,%1,%2,%3}, {%4,%5,%6,%7}, {%8,%9}, {%0,%1,%2,%3};"
        : "+f"(c[0]), "+f"(c[1]), "+f"(c[2]), "+f"(c[3])
        : "r"(a[0]), "r"(a[1]), "r"(a[2]), "r"(a[3]), "r"(b[0]), "r"(b[1]));
}

// FMA-pipe exp
__device__ __forceinline__ float fast_exp(float x) {
    x = fmaxf(x, -87.0f);
    float y = x * 1.4426950408889634f;
    float r = y + 12582912.0f;
    int   n = __float_as_int(r) - 0x4B400000;
    float f = y - (r - 12582912.0f);
    float p = 1.3333558146e-3f;
    p = fmaf(p, f, 9.6181291076e-3f);
    p = fmaf(p, f, 5.5504108664e-2f);
    p = fmaf(p, f, 2.4022650696e-1f);
    p = fmaf(p, f, 6.9314718056e-1f);
    p = fmaf(p, f, 1.0f);
    return __int_as_float(__float_as_int(p) + (n << 23));
}

// ======================= weight transpose + tf32 round + pair-interleave =======================
__global__ __launch_bounds__(256)
void transposeW(const float* __restrict__ src, int which, int K, int N)
{
    float* dst = (which == 0) ? g_wqT : (which == 1) ? g_wkvT : g_wpT;
    __shared__ float t[32][33];
    int bx = blockIdx.x * 32;   // N block
    int by = blockIdx.y * 32;   // K block
    int txl = threadIdx.x & 31;
    int tyl = threadIdx.x >> 5;
#pragma unroll
    for (int j = 0; j < 32; j += 8)
        t[tyl + j][txl] = src[(size_t)(by + tyl + j) * N + bx + txl];
    __syncthreads();
#pragma unroll
    for (int j = 0; j < 32; j += 8)
        dst[(size_t)(bx + tyl + j) * K + by + p8(txl)] = rnd_tf32(t[txl][tyl + j]);
}

// ======================= mma.sync tf32 GEMM (exact R6/R10 measured-best) =======================
// A: cp.async natural layout (stride 36), CVT at fragment load.
// B: cp.async raw copy of pre-interleaved weights (stride 40), LDS.64 fragments.
constexpr int BM = 128, BN = 128, BK = 32;
constexpr int SKA = 36;
constexpr int SKB = 40;
constexpr int A_WORDS = BM * SKA;               // 4608
constexpr int B_WORDS = BN * SKB;               // 5120
constexpr int STAGE_WORDS = A_WORDS + B_WORDS;  // 9728
constexpr int GEMM_SMEM = 2 * STAGE_WORDS * 4;  // 77824 bytes
constexpr int KT = KDIM / BK;                   // 24

template<int MODE>
__global__ __launch_bounds__(256, 2)
void gemm_tc(const float* __restrict__ A, const float* __restrict__ bias,
             float* __restrict__ Cout, int M)
{
    extern __shared__ float sm[];
    const uint32_t sb32 = smem_to_u32(sm);
    const int tid   = threadIdx.x;
    const int warp  = tid >> 5;
    const int lane  = tid & 31;
    const int group = lane >> 2;
    const int tig   = lane & 3;
    const int wm    = warp & 3;
    const int wn    = warp >> 2;
    const int row0  = blockIdx.y * BM;
    const int col0  = blockIdx.x * BN;

    const float* BT = (MODE == 0) ? g_wqT : (MODE == 1) ? g_wkvT : g_wpT;

    float acc[2][8][4];
#pragma unroll
    for (int mt = 0; mt < 2; mt++)
#pragma unroll
        for (int nt = 0; nt < 8; nt++)
#pragma unroll
            for (int c = 0; c < 4; c++) acc[mt][nt][c] = 0.f;

    const int lr  = tid >> 3;          // 0..31
    const int lk4 = (tid & 7) << 2;    // 0,4,...,28

    auto load_stage = [&](int kt, int s) {
        const uint32_t aoff = sb32 + (uint32_t)(s * STAGE_WORDS) * 4;
        const uint32_t boff = sb32 + (uint32_t)(s * STAGE_WORDS + A_WORDS) * 4;
        const int k0 = kt * BK;
#pragma unroll
        for (int it = 0; it < 4; it++) {
            int r = lr + it * 32;
            int grow = row0 + r;
            bool ok = grow < M;
            int gr = ok ? grow : 0;
            const float* src;
            if (MODE == 2) {
                int b_ = gr / NOUT;
                int n_ = gr - b_ * NOUT;
                int kk = k0 + lk4;
                int h = kk >> 6, dd = kk & 63;
                src = &g_att[(((size_t)(b_ * HH + h) * NOUT + n_) << 6) + dd];
            } else {
                src = &A[(size_t)gr * KDIM + k0 + lk4];
            }
            cp_async16p(aoff + (uint32_t)(r * SKA + lk4) * 4, src, ok);
        }
#pragma unroll
        for (int it = 0; it < 4; it++) {
            int r = lr + it * 32;
            cp_async16(boff + (uint32_t)(r * SKB + lk4) * 4,
                       &BT[(size_t)(col0 + r) * KDIM + k0 + lk4]);
        }
        CP_COMMIT();
    };

    load_stage(0, 0);

    for (int kt = 0; kt < KT; kt++) {
        const int cur = kt & 1;
        if (kt + 1 < KT) {
            load_stage(kt + 1, (kt + 1) & 1);
            CP_WAIT(1);
        } else {
            CP_WAIT(0);
        }
        __syncthreads();

        const float* As = sm + cur * STAGE_WORDS;
        const float* Bs = As + A_WORDS;

#pragma unroll
        for (int ks = 0; ks < 4; ks++) {
            const int kc = ks * 8 + tig;        // natural k (A)
            const int ko = ks * 8 + 2 * tig;    // interleaved k (B)
            uint32_t af[2][4];
#pragma unroll
            for (int mt = 0; mt < 2; mt++) {
                int r = wm * 32 + mt * 16 + group;
                af[mt][0] = to_tf32_rn(As[r * SKA + kc]);
                af[mt][1] = to_tf32_rn(As[(r + 8) * SKA + kc]);
                af[mt][2] = to_tf32_rn(As[r * SKA + kc + 4]);
                af[mt][3] = to_tf32_rn(As[(r + 8) * SKA + kc + 4]);
            }
#pragma unroll
            for (int nt = 0; nt < 8; nt++) {
                int n = wn * 64 + nt * 8 + group;
                float2 b = *(const float2*)&Bs[n * SKB + ko];
                uint32_t bf[2] = { __float_as_uint(b.x), __float_as_uint(b.y) };
                mma_tf32(acc[0][nt], af[0], bf);
                mma_tf32(acc[1][nt], af[1], bf);
            }
        }
        __syncthreads();
    }

    // ---- epilogue
#pragma unroll
    for (int mt = 0; mt < 2; mt++) {
#pragma unroll
        for (int half = 0; half < 2; half++) {
            int row = row0 + wm * 32 + mt * 16 + group + half * 8;
            if (row >= M) continue;
            int b_, n_;
            if (MODE == 0) { b_ = row / NQ;   n_ = row - b_ * NQ; }
            else if (MODE == 1) { b_ = row / NV; n_ = row - b_ * NV; }
            else { b_ = 0; n_ = 0; }
#pragma unroll
            for (int nt = 0; nt < 8; nt++) {
                int col = col0 + wn * 64 + nt * 8 + tig * 2;
                float v0 = acc[mt][nt][half * 2 + 0];
                float v1 = acc[mt][nt][half * 2 + 1];
                if (MODE == 0) {
                    int h = col >> 6, dd = col & 63;
                    float2 w = make_float2(v0 * 0.125f, v1 * 0.125f);
                    *(float2*)&g_q[(((size_t)(b_ * HH + h) * NQ + n_) << 6) + dd] = w;
                } else if (MODE == 1) {
                    float2 w = make_float2(v0, v1);
                    if (col < DIMD) {
                        int h = col >> 6, dd = col & 63;
                        *(float2*)&g_k[(((size_t)(b_ * HH + h) * NV + n_) << 6) + dd] = w;
                    } else {
                        int c2 = col - DIMD;
                        int h = c2 >> 6, dd = c2 & 63;
                        *(float2*)&g_v[(((size_t)(b_ * HH + h) * NV + n_) << 6) + dd] = w;
                    }
                } else {
                    float2 w = make_float2(v0 + bias[col], v1 + bias[col + 1]);
                    *(float2*)&Cout[(size_t)row * DIMD + col] = w;
                }
            }
        }
    }
}

// ======================= cls-token attention (unchanged) =======================
__global__ __launch_bounds__(256)
void cls_attn()
{
    __shared__ float qsh[64];
    __shared__ float ssh[NV];
    __shared__ float red[40];
    __shared__ float osh[4][64];

    const int bh   = blockIdx.x;
    const int tid  = threadIdx.x;
    const int lane = tid & 31;
    const int warp = tid >> 5;

    if (tid < 64) qsh[tid] = g_q[((size_t)bh * NQ) * 64 + tid];
    __syncthreads();

    for (int j = warp; j < NV; j += 8) {
        const float* kr = &g_k[((size_t)bh * NV + j) * 64];
        float p = qsh[lane] * kr[lane] + qsh[lane + 32] * kr[lane + 32];
#pragma unroll
        for (int o = 16; o > 0; o >>= 1) p += __shfl_xor_sync(0xffffffffu, p, o);
        if (lane == 0) ssh[j] = p;
    }
    __syncthreads();

    float m = -1e30f;
    for (int j = tid; j < NV; j += 256) m = fmaxf(m, ssh[j]);
#pragma unroll
    for (int o = 16; o > 0; o >>= 1) m = fmaxf(m, __shfl_xor_sync(0xffffffffu, m, o));
    if (lane == 0) red[warp] = m;
    __syncthreads();
    if (tid == 0) {
        float mm = red[0];
        for (int w = 1; w < 8; w++) mm = fmaxf(mm, red[w]);
        red[32] = mm;
    }
    __syncthreads();
    m = red[32];

    float s = 0.f;
    for (int j = tid; j < NV; j += 256) {
        float e = fast_exp(ssh[j] - m);
        ssh[j] = e;
        s += e;
    }
#pragma unroll
    for (int o = 16; o > 0; o >>= 1) s += __shfl_xor_sync(0xffffffffu, s, o);
    if (lane == 0) red[8 + warp] = s;
    __syncthreads();
    if (tid == 0) {
        float ss = 0.f;
        for (int w = 0; w < 8; w++) ss += red[8 + w];
        red[33] = 1.f / ss;
    }
    __syncthreads();
    const float inv = red[33];

    const int g = tid >> 6, dd = tid & 63;
    float o = 0.f;
    for (int j = g; j < NV; j += 4)
        o = fmaf(ssh[j], g_v[((size_t)bh * NV + j) * 64 + dd], o);
    osh[g][dd] = o;
    __syncthreads();
    if (tid < 64) {
        float r = (osh[0][tid] + osh[1][tid] + osh[2][tid] + osh[3][tid]) * inv;
        g_att[((size_t)bh * NOUT) * 64 + tid] = r;
    }
}

// ======================= fine attention — R11 version (kept) ===========
constexpr int QWN = 68;   // Q natural [64][68], two buffers
constexpr int KW  = 72;   // Ks [224][72] pair-interleaved d
constexpr int VWN = 72;   // Vn [200][72] natural (rows 196..199 zero)
constexpr int SW  = 228;  // Ss [64][228]
constexpr int Q0_OFF = 0;
constexpr int Q1_OFF = Q0_OFF + 64 * QWN;   // 4352
constexpr int K_OFF  = Q1_OFF + 64 * QWN;   // 8704
constexpr int V_OFF  = K_OFF + 224 * KW;    // 24832
constexpr int S_OFF  = V_OFF + 200 * VWN;   // 39232
constexpr int I_OFF  = S_OFF + 64 * SW;     // 53824
constexpr int FINE_SMEM = (I_OFF + 64) * 4; // 215552 bytes

__global__ __launch_bounds__(512, 1)
void fine_attn()
{
    extern __shared__ float smf[];
    float* Ks = smf + K_OFF;
    float* Vn = smf + V_OFF;
    float* Ss = smf + S_OFF;
    float* Iv = smf + I_OFF;

    const int bh    = blockIdx.x >> 3;
    const int f     = blockIdx.x & 7;
    const int tid   = threadIdx.x;
    const int warp  = tid >> 5;      // 0..15
    const int lane  = tid & 31;
    const int group = lane >> 2;
    const int tig   = lane & 3;
    const int wm    = warp & 3;
    const int wn    = warp >> 2;

    const uint32_t sb32 = smem_to_u32(smf);
    const float* kg = &g_k[((size_t)bh * NV + (size_t)f * NKC) * 64];
    const float* vg = &g_v[((size_t)bh * NV + (size_t)f * NKC) * 64];
    const float* qg = &g_q[((size_t)bh * NQ + 1) * 64];

    // ---- V: raw cp.async into natural [196][72] (cols 64..71 unused)
    for (int idx = tid; idx < NKC * 16; idx += 512) {
        int j = idx >> 4, c4 = (idx & 15) << 2;
        cp_async16(sb32 + (uint32_t)(V_OFF + j * VWN + c4) * 4, &vg[j * 64 + c4]);
    }
    CP_COMMIT();

    auto loadQ = [&](int qc, int buf) {
        const int rows = (qc == 3) ? (NKC - 192) : 64;
        const uint32_t qoff = sb32 + (uint32_t)((buf ? Q1_OFF : Q0_OFF)) * 4;
#pragma unroll
        for (int it = 0; it < 2; it++) {
            int idx = tid + it * 512;
            int r = idx >> 4, c4 = (idx & 15) << 2;
            cp_async16p(qoff + (uint32_t)(r * QWN + c4) * 4,
                        &qg[(size_t)(qc * 64 + r) * 64 + c4], r < rows);
        }
        CP_COMMIT();
    };
    loadQ(0, 0);

    // ---- K: LDG + interleave + round (pad rows 196..223 zero)
    for (int u = tid; u < 224 * 8; u += 512) {
        int r = u >> 3, g = u & 7;
        float4 v0 = make_float4(0.f, 0.f, 0.f, 0.f), v1 = v0;
        if (r < NKC) {
            v0 = f4_rnd(*(const float4*)&kg[r * 64 + g * 8]);
            v1 = f4_rnd(*(const float4*)&kg[r * 64 + g * 8 + 4]);
        }
        sts_pair8(&Ks[r * KW + g * 8], v0, v1);
    }
    // ---- V pad rows 196..199 zero (full 72-word rows)
    for (int idx = tid; idx < 4 * 18; idx += 512) {
        int r = 196 + idx / 18, c4 = (idx % 18) * 4;
        *(float4*)&Vn[r * VWN + c4] = make_float4(0.f, 0.f, 0.f, 0.f);
    }

    for (int qc = 0; qc < 4; qc++) {
        if (qc < 3) loadQ(qc + 1, (qc + 1) & 1);
        if (qc < 3) { CP_WAIT(1); } else { CP_WAIT(0); }
        __syncthreads();

        const float* Qc = smf + ((qc & 1) ? Q1_OFF : Q0_OFF);

        // ---- S = Q @ K^T : warps 4M x 4N, warp tile 16 x 56
        {
            float acc[7][4];
#pragma unroll
            for (int nt = 0; nt < 7; nt++)
#pragma unroll
                for (int c = 0; c < 4; c++) acc[nt][c] = 0.f;

#pragma unroll
            for (int ks = 0; ks < 8; ks++) {
                const int kc = ks * 8 + tig;        // natural (Q)
                const int ko = ks * 8 + 2 * tig;    // interleaved (K)
                const int r = wm * 16 + group;
                uint32_t af[4];
                af[0] = to_tf32_rn(Qc[r * QWN + kc]);
                af[1] = to_tf32_rn(Qc[(r + 8) * QWN + kc]);
                af[2] = to_tf32_rn(Qc[r * QWN + kc + 4]);
                af[3] = to_tf32_rn(Qc[(r + 8) * QWN + kc + 4]);
#pragma unroll
                for (int nt = 0; nt < 7; nt++) {
                    int n = wn * 56 + nt * 8 + group;
                    float2 b = *(const float2*)&Ks[n * KW + ko];
                    uint32_t bf[2] = { __float_as_uint(b.x), __float_as_uint(b.y) };
                    mma_tf32(acc[nt], af, bf);
                }
            }
            const int r = wm * 16 + group;
#pragma unroll
            for (int nt = 0; nt < 7; nt++) {
                int n = wn * 56 + nt * 8 + tig * 2;
                *(float2*)&Ss[r * SW + n]       = make_float2(acc[nt][0], acc[nt][1]);
                *(float2*)&Ss[(r + 8) * SW + n] = make_float2(acc[nt][2], acc[nt][3]);
            }
        }
        __syncthreads();

        // ---- softmax: 4 rows per warp, ILP-batched; normalization deferred
        {
            float mx[4], sum[4];
#pragma unroll
            for (int rr = 0; rr < 4; rr++) mx[rr] = -1e30f;
#pragma unroll
            for (int it = 0; it < 7; it++) {
                int j = lane + it * 32;
                if (j < NKC) {
#pragma unroll
                    for (int rr = 0; rr < 4; rr++)
                        mx[rr] = fmaxf(mx[rr], Ss[(warp * 4 + rr) * SW + j]);
                }
            }
#pragma unroll
            for (int o = 16; o > 0; o >>= 1)
#pragma unroll
                for (int rr = 0; rr < 4; rr++)
                    mx[rr] = fmaxf(mx[rr], __shfl_xor_sync(0xffffffffu, mx[rr], o));
#pragma unroll
            for (int rr = 0; rr < 4; rr++) sum[rr] = 0.f;
#pragma unroll
            for (int it = 0; it < 7; it++) {
                int j = lane + it * 32;
                if (j < NKC) {
#pragma unroll
                    for (int rr = 0; rr < 4; rr++) {
                        float* sp = &Ss[(warp * 4 + rr) * SW + j];
                        float e = fast_exp(*sp - mx[rr]);
                        *sp = rnd_tf32(e);
                        sum[rr] += e;
                    }
                }
            }
#pragma unroll
            for (int o = 16; o > 0; o >>= 1)
#pragma unroll
                for (int rr = 0; rr < 4; rr++)
                    sum[rr] += __shfl_xor_sync(0xffffffffu, sum[rr], o);
            if (lane == 0) {
#pragma unroll
                for (int rr = 0; rr < 4; rr++) Iv[warp * 4 + rr] = 1.f / sum[rr];
            }
        }
        __syncthreads();

        // ---- O = P @ V : warps 4M x 4N, warp tile 16 x 16; V natural (rows 196..199 = 0)
        {
            float acc[2][4];
#pragma unroll
            for (int nt = 0; nt < 2; nt++)
#pragma unroll
                for (int c = 0; c < 4; c++) acc[nt][c] = 0.f;

            for (int ks = 0; ks < 25; ks++) {
                const int kc = ks * 8 + tig;
                const int r = wm * 16 + group;
                uint32_t af[4] = {
                    __float_as_uint(Ss[r * SW + kc]),
                    __float_as_uint(Ss[(r + 8) * SW + kc]),
                    __float_as_uint(Ss[r * SW + kc + 4]),
                    __float_as_uint(Ss[(r + 8) * SW + kc + 4]) };
#pragma unroll
                for (int nt = 0; nt < 2; nt++) {
                    int n = wn * 16 + nt * 8 + group;
                    uint32_t bf[2];
                    bf[0] = to_tf32_rn(Vn[(ks * 8 + tig) * VWN + n]);
                    bf[1] = to_tf32_rn(Vn[(ks * 8 + tig + 4) * VWN + n]);
                    mma_tf32(acc[nt], af, bf);
                }
            }
#pragma unroll
            for (int half = 0; half < 2; half++) {
                int rl = wm * 16 + group + half * 8;
                int qrow = qc * 64 + rl;
                if (qrow >= NKC) continue;
                float iv = Iv[rl];
                size_t base = ((size_t)bh * NOUT + 1 + (size_t)f * NKC + qrow) * 64;
#pragma unroll
                for (int nt = 0; nt < 2; nt++) {
                    int col = wn * 16 + nt * 8 + tig * 2;
                    float2 w = make_float2(acc[nt][half * 2] * iv,
                                           acc[nt][half * 2 + 1] * iv);
                    *(float2*)&g_att[base + col] = w;
                }
            }
        }
        __syncthreads();
    }
}

// ======================= launch =======================
extern "C" void kernel_launch(void* const* d_in, const int* in_sizes, int n_in,
                              void* d_out, int out_size)
{
    const float* x        = (const float*)d_in[0];
    const float* question = (const float*)d_in[1];
    const float* Wq       = (const float*)d_in[2];
    const float* Wkv      = (const float*)d_in[3];
    const float* Wproj    = (const float*)d_in[4];
    const float* bproj    = (const float*)d_in[5];
    float* out = (float*)d_out;

    cudaFuncSetAttribute(fine_attn, cudaFuncAttributeMaxDynamicSharedMemorySize, FINE_SMEM);
    cudaFuncSetAttribute(gemm_tc<0>, cudaFuncAttributeMaxDynamicSharedMemorySize, GEMM_SMEM);
    cudaFuncSetAttribute(gemm_tc<1>, cudaFuncAttributeMaxDynamicSharedMemorySize, GEMM_SMEM);
    cudaFuncSetAttribute(gemm_tc<2>, cudaFuncAttributeMaxDynamicSharedMemorySize, GEMM_SMEM);

    // weight prep
    transposeW<<<dim3(768 / 32, 768 / 32), 256>>>(Wq, 0, 768, 768);
    transposeW<<<dim3(1536 / 32, 768 / 32), 256>>>(Wkv, 1, 768, 1536);
    transposeW<<<dim3(768 / 32, 768 / 32), 256>>>(Wproj, 2, 768, 768);

    gemm_tc<0><<<dim3(768 / BN, (BB * NQ + BM - 1) / BM), 256, GEMM_SMEM>>>(
        question, nullptr, nullptr, BB * NQ);

    gemm_tc<1><<<dim3(1536 / BN, (BB * NV) / BM), 256, GEMM_SMEM>>>(
        x, nullptr, nullptr, BB * NV);

    cls_attn<<<BHN, 256>>>();
    fine_attn<<<BHN * FF, 512, FINE_SMEM>>>();

    gemm_tc<2><<<dim3(768 / BN, (BB * NOUT + BM - 1) / BM), 256, GEMM_SMEM>>>(
        nullptr, bproj, out, BB * NOUT);
}